// round 2
// baseline (speedup 1.0000x reference)
#include <cuda_runtime.h>
#include <math.h>

#define MAX_NODES 50000
#define MAX_EDGES 500000

// ---- scratch (static device globals; no runtime allocation) ----
__device__ float g_la[MAX_NODES * 32];            // l_a projected per node
__device__ float g_lv[MAX_NODES * 96];            // l_v projected per node, layout [node][i][c] (i=0..2, c=0..31)
__device__ float g_psiA0[(size_t)MAX_EDGES * 128]; // pre-MLP psi_a
__device__ float g_h1[(size_t)MAX_EDGES * 128];
__device__ float g_h2[(size_t)MAX_EDGES * 128];

// ============================================================
// Kernel 1: node projections  l_a = x_a @ W_L0^T, l_v = einsum(x_v, W_L1)
// one warp per node, lane = channel c
// ============================================================
__global__ void node_proj_kernel(const float* __restrict__ x_a,
                                 const float* __restrict__ x_v,
                                 const float* __restrict__ W_L0,
                                 const float* __restrict__ W_L1,
                                 int n_nodes)
{
    __shared__ float sWL0T[128 * 32];  // [d][c]
    __shared__ float sWL1T[32 * 32];   // [d][c]
    __shared__ float sxa[8][128];
    __shared__ float sxv[8][96];

    int tid = threadIdx.x;
    for (int idx = tid; idx < 4096; idx += 256) { int c = idx >> 7, d = idx & 127; sWL0T[d * 32 + c] = W_L0[idx]; }
    for (int idx = tid; idx < 1024; idx += 256) { int c = idx >> 5, d = idx & 31;  sWL1T[d * 32 + c] = W_L1[idx]; }
    __syncthreads();

    int w = tid >> 5, c = tid & 31;
    int node = blockIdx.x * 8 + w;
    if (node >= n_nodes) return;

    *(float4*)&sxa[w][c * 4] = *(const float4*)(x_a + (size_t)node * 128 + c * 4);
    if (c < 24) *(float4*)&sxv[w][c * 4] = *(const float4*)(x_v + (size_t)node * 96 + c * 4);
    __syncwarp();

    float la = 0.f;
#pragma unroll 8
    for (int d = 0; d < 128; d++) la += sxa[w][d] * sWL0T[d * 32 + c];

    float lv0 = 0.f, lv1 = 0.f, lv2 = 0.f;
#pragma unroll 8
    for (int d = 0; d < 32; d++) {
        float wl = sWL1T[d * 32 + c];
        lv0 += sxv[w][d * 3 + 0] * wl;
        lv1 += sxv[w][d * 3 + 1] * wl;
        lv2 += sxv[w][d * 3 + 2] * wl;
    }
    g_la[node * 32 + c] = la;
    g_lv[node * 96 + 0 + c]  = lv0;
    g_lv[node * 96 + 32 + c] = lv1;
    g_lv[node * 96 + 64 + c] = lv2;
}

// ============================================================
// Kernel 2: per-edge (one warp per edge, lane = channel c)
// radial encode, tens_sigmoid, tensor products, psiA0 to scratch,
// psi_v atomic scatter into B_v
// ============================================================
__global__ void edge_kernel(const float* __restrict__ r_ij,
                            const int* __restrict__ src,
                            const int* __restrict__ dst,
                            const float* __restrict__ W_enc,
                            const float* __restrict__ b_enc,
                            const float* __restrict__ Wy000,
                            const float* __restrict__ Wy110,
                            const float* __restrict__ Wy011,
                            const float* __restrict__ Wy101,
                            const float* __restrict__ Wy111,
                            float* __restrict__ Bv,
                            int n_edges)
{
    __shared__ float sWencT[8 * 32];    // [k][c]
    __shared__ float sbenc[32];
    __shared__ float sWy000T[32 * 128]; // [c][j]
    __shared__ float sWy110T[32 * 128]; // [c][j]
    __shared__ float sWy011T[32 * 32];  // [c][d]
    __shared__ float sWy101T[32 * 32];
    __shared__ float sWy111T[32 * 32];

    int tid = threadIdx.x;
    for (int idx = tid; idx < 4096; idx += 256) {
        int j = idx >> 5, cc = idx & 31;
        sWy000T[cc * 128 + j] = Wy000[idx];
        sWy110T[cc * 128 + j] = Wy110[idx];
    }
    for (int idx = tid; idx < 1024; idx += 256) {
        int dd = idx >> 5, cc = idx & 31;
        sWy011T[cc * 32 + dd] = Wy011[idx];
        sWy101T[cc * 32 + dd] = Wy101[idx];
        sWy111T[cc * 32 + dd] = Wy111[idx];
    }
    if (tid < 256) { int cch = tid >> 3, k = tid & 7; sWencT[k * 32 + cch] = W_enc[tid]; }
    if (tid < 32) sbenc[tid] = b_enc[tid];
    __syncthreads();

    int w = tid >> 5, c = tid & 31;
    int e = blockIdx.x * 8 + w;
    if (e >= n_edges) return;

    float r0 = __ldg(r_ij + (size_t)e * 3 + 0);
    float r1 = __ldg(r_ij + (size_t)e * 3 + 1);
    float r2 = __ldg(r_ij + (size_t)e * 3 + 2);
    float rr = sqrtf(r0 * r0 + r1 * r1 + r2 * r2);

    // 8 gaussian basis values, computed by lanes 0..7 then broadcast
    float ex = 0.f;
    if (c < 8) {
        float ctr = (5.0f / 7.0f) * (float)c;
        float dd = (rr - ctr) * (8.0f / 5.0f);   // / width, width = 5/8
        ex = expf(-dd * dd);
    }
    float renc = sbenc[c];
#pragma unroll
    for (int k = 0; k < 8; k++)
        renc += __shfl_sync(0xffffffffu, ex, k) * sWencT[k * 32 + c];

    // tens_sigmoid on 1.4 * r
    float nn = 1.4f * rr;
    float th = tanhf(nn) / fmaxf(nn, 1e-6f);
    float rs0 = 1.4f * r0 * th, rs1 = 1.4f * r1 * th, rs2 = 1.4f * r2 * th;

    int dn = __ldg(dst + e);
    float la = __ldg(g_la + (size_t)dn * 32 + c);
    float t0 = renc * __ldg(g_lv + (size_t)dn * 96 + 0 + c);
    float t1 = renc * __ldg(g_lv + (size_t)dn * 96 + 32 + c);
    float t2 = renc * __ldg(g_lv + (size_t)dn * 96 + 64 + c);

    float y000 = la * renc;                            // l_a * phi_a
    float y110 = t0 * rs0 + t1 * rs1 + t2 * rs2;       // dot(l_v, phi_v)
    // u = t x r_s = cross(l_v, phi_v)
    float u0 = t1 * rs2 - t2 * rs1;
    float u1 = t2 * rs0 - t0 * rs2;
    float u2 = t0 * rs1 - t1 * rs0;

    float4 pa = make_float4(0.f, 0.f, 0.f, 0.f);   // psiA0[c*4 .. c*4+3]
    float s000 = 0.f, av0 = 0.f, av1 = 0.f, av2 = 0.f;

#pragma unroll 8
    for (int cc = 0; cc < 32; cc++) {
        float y0 = __shfl_sync(0xffffffffu, y000, cc);
        float y1 = __shfl_sync(0xffffffffu, y110, cc);
        float q0 = __shfl_sync(0xffffffffu, t0, cc);
        float q1 = __shfl_sync(0xffffffffu, t1, cc);
        float q2 = __shfl_sync(0xffffffffu, t2, cc);
        float v0 = __shfl_sync(0xffffffffu, u0, cc);
        float v1 = __shfl_sync(0xffffffffu, u1, cc);
        float v2 = __shfl_sync(0xffffffffu, u2, cc);

        float4 w0 = *(const float4*)&sWy000T[cc * 128 + c * 4];
        float4 w1 = *(const float4*)&sWy110T[cc * 128 + c * 4];
        pa.x += y0 * w0.x + y1 * w1.x;
        pa.y += y0 * w0.y + y1 * w1.y;
        pa.z += y0 * w0.z + y1 * w1.z;
        pa.w += y0 * w0.w + y1 * w1.w;

        float wa = sWy011T[cc * 32 + c];
        float wb = sWy101T[cc * 32 + c];
        float wc = sWy111T[cc * 32 + c];
        s000 += wa * y0;
        av0 += wb * q0 + wc * v0;
        av1 += wb * q1 + wc * v1;
        av2 += wb * q2 + wc * v2;
    }

    *(float4*)(g_psiA0 + (size_t)e * 128 + c * 4) = pa;

    int sn = __ldg(src + e);
    float* bv = Bv + (size_t)sn * 96 + c * 3;
    atomicAdd(bv + 0, 0.1f * (rs0 * s000 + av0));
    atomicAdd(bv + 1, 0.1f * (rs1 * s000 + av1));
    atomicAdd(bv + 2, 0.1f * (rs2 * s000 + av2));
}

// ============================================================
// GEMM: C[E x 128] = act(A[E x 128] @ W^T + b)
// MODE 0: A=g_psiA0 -> g_h1 (leaky)
// MODE 1: A=g_h1    -> g_h2 (leaky)
// MODE 2: A=g_h2; epilogue: 0.1*(g_psiA0 + A@Wm3^T) atomically into B_a[src]
// 128x128 block tile, 256 threads, 8x8 per thread, fp32
// ============================================================
template <int MODE>
__global__ void __launch_bounds__(256, 1) gemm128(const float* __restrict__ W,
                                                  const float* __restrict__ bias,
                                                  const int* __restrict__ src,
                                                  float* __restrict__ Ba,
                                                  int n_edges)
{
    extern __shared__ float sm[];
    float* Ast = sm;               // [k][m], stride 132
    float* Ws  = sm + 128 * 132;   // [k][j], stride 132
    __shared__ float sb[128];

    const float* A = (MODE == 0) ? g_psiA0 : (MODE == 1) ? g_h1 : g_h2;
    float* Out = (MODE == 0) ? g_h1 : g_h2;

    int tid = threadIdx.x;
    int base = blockIdx.x * 128;

    // W transposed into smem
#pragma unroll
    for (int i = 0; i < 16; i++) {
        int f = tid + i * 256;
        int j = f >> 5, k4 = f & 31;
        float4 v = *(const float4*)(W + j * 128 + k4 * 4);
        Ws[(k4 * 4 + 0) * 132 + j] = v.x;
        Ws[(k4 * 4 + 1) * 132 + j] = v.y;
        Ws[(k4 * 4 + 2) * 132 + j] = v.z;
        Ws[(k4 * 4 + 3) * 132 + j] = v.w;
    }
    // A tile transposed into smem
#pragma unroll
    for (int i = 0; i < 16; i++) {
        int f = tid + i * 256;
        int m = f >> 5, k4 = f & 31;
        int e = base + m;
        float4 v = make_float4(0.f, 0.f, 0.f, 0.f);
        if (e < n_edges) v = *(const float4*)(A + (size_t)e * 128 + k4 * 4);
        Ast[(k4 * 4 + 0) * 132 + m] = v.x;
        Ast[(k4 * 4 + 1) * 132 + m] = v.y;
        Ast[(k4 * 4 + 2) * 132 + m] = v.z;
        Ast[(k4 * 4 + 3) * 132 + m] = v.w;
    }
    if (MODE < 2 && tid < 128) sb[tid] = bias[tid];
    __syncthreads();

    int tx = tid & 15, ty = tid >> 4;
    int row0 = ty * 8, col0 = tx * 8;

    float acc[8][8];
#pragma unroll
    for (int r = 0; r < 8; r++)
#pragma unroll
        for (int q = 0; q < 8; q++) acc[r][q] = 0.f;

#pragma unroll 4
    for (int k = 0; k < 128; k++) {
        float4 a0 = *(const float4*)&Ast[k * 132 + row0];
        float4 a1 = *(const float4*)&Ast[k * 132 + row0 + 4];
        float4 b0 = *(const float4*)&Ws[k * 132 + col0];
        float4 b1 = *(const float4*)&Ws[k * 132 + col0 + 4];
        float ar[8] = {a0.x, a0.y, a0.z, a0.w, a1.x, a1.y, a1.z, a1.w};
        float br[8] = {b0.x, b0.y, b0.z, b0.w, b1.x, b1.y, b1.z, b1.w};
#pragma unroll
        for (int r = 0; r < 8; r++)
#pragma unroll
            for (int q = 0; q < 8; q++)
                acc[r][q] += ar[r] * br[q];
    }

    if (MODE < 2) {
#pragma unroll
        for (int r = 0; r < 8; r++) {
            int e = base + row0 + r;
            if (e >= n_edges) continue;
            float o[8];
#pragma unroll
            for (int q = 0; q < 8; q++) {
                float v = acc[r][q] + sb[col0 + q];
                o[q] = (v >= 0.f) ? v : 0.1f * v;
            }
            *(float4*)(Out + (size_t)e * 128 + col0)     = make_float4(o[0], o[1], o[2], o[3]);
            *(float4*)(Out + (size_t)e * 128 + col0 + 4) = make_float4(o[4], o[5], o[6], o[7]);
        }
    } else {
#pragma unroll
        for (int r = 0; r < 8; r++) {
            int e = base + row0 + r;
            if (e >= n_edges) continue;
            int s = __ldg(src + e);
            float4 p0 = *(const float4*)(g_psiA0 + (size_t)e * 128 + col0);
            float4 p1 = *(const float4*)(g_psiA0 + (size_t)e * 128 + col0 + 4);
            float pr[8] = {p0.x, p0.y, p0.z, p0.w, p1.x, p1.y, p1.z, p1.w};
            float* bp = Ba + (size_t)s * 128 + col0;
#pragma unroll
            for (int q = 0; q < 8; q++)
                atomicAdd(bp + q, 0.1f * (acc[r][q] + pr[q]));
        }
    }
}

// ============================================================
extern "C" void kernel_launch(void* const* d_in, const int* in_sizes, int n_in,
                              void* d_out, int out_size)
{
    const float* x_a   = (const float*)d_in[0];
    const float* x_v   = (const float*)d_in[1];
    const float* r_ij  = (const float*)d_in[2];
    const int*   src   = (const int*)d_in[3];
    const int*   dst   = (const int*)d_in[4];
    const float* W_L0  = (const float*)d_in[5];
    const float* W_L1  = (const float*)d_in[6];
    const float* W_enc = (const float*)d_in[7];
    const float* b_enc = (const float*)d_in[8];
    const float* Wy000 = (const float*)d_in[9];
    const float* Wy110 = (const float*)d_in[10];
    const float* Wy011 = (const float*)d_in[11];
    const float* Wy101 = (const float*)d_in[12];
    const float* Wy111 = (const float*)d_in[13];
    const float* Wm1   = (const float*)d_in[14];
    const float* bm1   = (const float*)d_in[15];
    const float* Wm2   = (const float*)d_in[16];
    const float* bm2   = (const float*)d_in[17];
    const float* Wm3   = (const float*)d_in[18];

    int n_nodes = in_sizes[0] / 128;
    int n_edges = in_sizes[2] / 3;

    float* Ba = (float*)d_out;
    float* Bv = Ba + (size_t)n_nodes * 128;

    cudaMemsetAsync(d_out, 0, (size_t)out_size * sizeof(float), 0);

    node_proj_kernel<<<(n_nodes + 7) / 8, 256>>>(x_a, x_v, W_L0, W_L1, n_nodes);

    edge_kernel<<<(n_edges + 7) / 8, 256>>>(r_ij, src, dst, W_enc, b_enc,
                                            Wy000, Wy110, Wy011, Wy101, Wy111,
                                            Bv, n_edges);

    int smem = 2 * 128 * 132 * (int)sizeof(float);
    cudaFuncSetAttribute(gemm128<0>, cudaFuncAttributeMaxDynamicSharedMemorySize, smem);
    cudaFuncSetAttribute(gemm128<1>, cudaFuncAttributeMaxDynamicSharedMemorySize, smem);
    cudaFuncSetAttribute(gemm128<2>, cudaFuncAttributeMaxDynamicSharedMemorySize, smem);

    int gb = (n_edges + 127) / 128;
    gemm128<0><<<gb, 256, smem>>>(Wm1, bm1, src, Ba, n_edges);
    gemm128<1><<<gb, 256, smem>>>(Wm2, bm2, src, Ba, n_edges);
    gemm128<2><<<gb, 256, smem>>>(Wm3, (const float*)nullptr, src, Ba, n_edges);
}

// round 5
// speedup vs baseline: 2.2790x; 2.2790x over previous
#include <cuda_runtime.h>
#include <cuda_fp16.h>
#include <math.h>
#include <stdint.h>

#define MAX_NODES 50000
#define MAX_EDGES 500000

// ---- scratch (static device globals; no runtime allocation) ----
__device__ float g_la[MAX_NODES * 32];
__device__ float g_lv[MAX_NODES * 96];
__device__ float g_psiA0[(size_t)MAX_EDGES * 128];
// f16 hi/lo weight copies, plain row-major [layer][hi/lo][n][k]
__device__ __align__(16) __half g_Whl[3][2][128 * 128];

// ============================================================
// helpers
// ============================================================
__device__ __forceinline__ uint32_t smem_u32(const void* p) {
    uint32_t a;
    asm("{ .reg .u64 t; cvta.to.shared.u64 t, %1; cvt.u32.u64 %0, t; }" : "=r"(a) : "l"(p));
    return a;
}

__device__ __forceinline__ void ldsm_x4(uint32_t r[4], uint32_t addr) {
    asm volatile("ldmatrix.sync.aligned.m8n8.x4.shared.b16 {%0,%1,%2,%3}, [%4];"
                 : "=r"(r[0]), "=r"(r[1]), "=r"(r[2]), "=r"(r[3]) : "r"(addr));
}

__device__ __forceinline__ void mma16816(float c[4], const uint32_t a[4], const uint32_t b[2]) {
    asm volatile("mma.sync.aligned.m16n8k16.row.col.f32.f16.f16.f32 "
                 "{%0,%1,%2,%3}, {%4,%5,%6,%7}, {%8,%9}, {%0,%1,%2,%3};"
                 : "+f"(c[0]), "+f"(c[1]), "+f"(c[2]), "+f"(c[3])
                 : "r"(a[0]), "r"(a[1]), "r"(a[2]), "r"(a[3]), "r"(b[0]), "r"(b[1]));
}

#define CP_ASYNC16(dst, src) \
    asm volatile("cp.async.cg.shared.global [%0], [%1], 16;" :: "r"(dst), "l"(src) : "memory")
#define CP_COMMIT() asm volatile("cp.async.commit_group;" ::: "memory")
#define CP_WAIT0()  asm volatile("cp.async.wait_group 0;" ::: "memory")

__device__ __forceinline__ void red_v2(float* p, float a, float b) {
    asm volatile("red.global.add.v2.f32 [%0], {%1,%2};" :: "l"(p), "f"(a), "f"(b) : "memory");
}

__device__ __forceinline__ uint32_t pack_h2(__half a, __half b) {
    __half2 t = __halves2half2(a, b);
    return *reinterpret_cast<uint32_t*>(&t);
}

// ============================================================
// Kernel 0: weight prep — split Wm[l] into f16 hi/lo (row-major)
// ============================================================
__global__ void wprep_kernel(const float* __restrict__ W1,
                             const float* __restrict__ W2,
                             const float* __restrict__ W3)
{
    const float* Ws = (blockIdx.x == 0) ? W1 : (blockIdx.x == 1) ? W2 : W3;
    for (int idx = threadIdx.x; idx < 128 * 128; idx += blockDim.x) {
        float wv = Ws[idx];
        __half hi = __float2half_rn(wv);
        __half lo = __float2half_rn(wv - __half2float(hi));
        g_Whl[blockIdx.x][0][idx] = hi;
        g_Whl[blockIdx.x][1][idx] = lo;
    }
}

// ============================================================
// Kernel 1: node projections
// ============================================================
__global__ void node_proj_kernel(const float* __restrict__ x_a,
                                 const float* __restrict__ x_v,
                                 const float* __restrict__ W_L0,
                                 const float* __restrict__ W_L1,
                                 int n_nodes)
{
    __shared__ float sWL0T[128 * 32];
    __shared__ float sWL1T[32 * 32];
    __shared__ float sxa[8][128];
    __shared__ float sxv[8][96];

    int tid = threadIdx.x;
    for (int idx = tid; idx < 4096; idx += 256) { int c = idx >> 7, d = idx & 127; sWL0T[d * 32 + c] = W_L0[idx]; }
    for (int idx = tid; idx < 1024; idx += 256) { int c = idx >> 5, d = idx & 31;  sWL1T[d * 32 + c] = W_L1[idx]; }
    __syncthreads();

    int w = tid >> 5, c = tid & 31;
    int node = blockIdx.x * 8 + w;
    if (node >= n_nodes) return;

    *(float4*)&sxa[w][c * 4] = *(const float4*)(x_a + (size_t)node * 128 + c * 4);
    if (c < 24) *(float4*)&sxv[w][c * 4] = *(const float4*)(x_v + (size_t)node * 96 + c * 4);
    __syncwarp();

    float la = 0.f;
#pragma unroll 8
    for (int d = 0; d < 128; d++) la += sxa[w][d] * sWL0T[d * 32 + c];

    float lv0 = 0.f, lv1 = 0.f, lv2 = 0.f;
#pragma unroll 8
    for (int d = 0; d < 32; d++) {
        float wl = sWL1T[d * 32 + c];
        lv0 += sxv[w][d * 3 + 0] * wl;
        lv1 += sxv[w][d * 3 + 1] * wl;
        lv2 += sxv[w][d * 3 + 2] * wl;
    }
    g_la[node * 32 + c] = la;
    g_lv[node * 96 + 0 + c]  = lv0;
    g_lv[node * 96 + 32 + c] = lv1;
    g_lv[node * 96 + 64 + c] = lv2;
}

// ============================================================
// Kernel 2: per-edge tensor products (4 edges per warp)
// ============================================================
__global__ void edge_kernel(const float* __restrict__ r_ij,
                            const int* __restrict__ src,
                            const int* __restrict__ dst,
                            const float* __restrict__ W_enc,
                            const float* __restrict__ b_enc,
                            const float* __restrict__ Wy000,
                            const float* __restrict__ Wy110,
                            const float* __restrict__ Wy011,
                            const float* __restrict__ Wy101,
                            const float* __restrict__ Wy111,
                            float* __restrict__ Bv,
                            int n_edges)
{
    __shared__ float sWencT[8 * 32];
    __shared__ float sbenc[32];
    __shared__ float sWy000T[32 * 128];
    __shared__ float sWy110T[32 * 128];
    __shared__ float sWy011T[32 * 32];
    __shared__ float sWy101T[32 * 32];
    __shared__ float sWy111T[32 * 32];

    int tid = threadIdx.x;
    for (int idx = tid; idx < 4096; idx += 256) {
        int j = idx >> 5, cc = idx & 31;
        sWy000T[cc * 128 + j] = Wy000[idx];
        sWy110T[cc * 128 + j] = Wy110[idx];
    }
    for (int idx = tid; idx < 1024; idx += 256) {
        int dd = idx >> 5, cc = idx & 31;
        sWy011T[cc * 32 + dd] = Wy011[idx];
        sWy101T[cc * 32 + dd] = Wy101[idx];
        sWy111T[cc * 32 + dd] = Wy111[idx];
    }
    if (tid < 256) { int cch = tid >> 3, k = tid & 7; sWencT[k * 32 + cch] = W_enc[tid]; }
    if (tid < 32) sbenc[tid] = b_enc[tid];
    __syncthreads();

    int w = tid >> 5, c = tid & 31;

    for (int ei = 0; ei < 4; ei++) {
        int e = blockIdx.x * 32 + ei * 8 + w;
        if (e >= n_edges) continue;

        float r0 = __ldg(r_ij + (size_t)e * 3 + 0);
        float r1 = __ldg(r_ij + (size_t)e * 3 + 1);
        float r2 = __ldg(r_ij + (size_t)e * 3 + 2);
        float rr = sqrtf(r0 * r0 + r1 * r1 + r2 * r2);

        float ex = 0.f;
        if (c < 8) {
            float ctr = (5.0f / 7.0f) * (float)c;
            float dd = (rr - ctr) * (8.0f / 5.0f);
            ex = expf(-dd * dd);
        }
        float renc = sbenc[c];
#pragma unroll
        for (int k = 0; k < 8; k++)
            renc += __shfl_sync(0xffffffffu, ex, k) * sWencT[k * 32 + c];

        float nn = 1.4f * rr;
        float th = tanhf(nn) / fmaxf(nn, 1e-6f);
        float rs0 = 1.4f * r0 * th, rs1 = 1.4f * r1 * th, rs2 = 1.4f * r2 * th;

        int dn = __ldg(dst + e);
        float la = __ldg(g_la + (size_t)dn * 32 + c);
        float t0 = renc * __ldg(g_lv + (size_t)dn * 96 + 0 + c);
        float t1 = renc * __ldg(g_lv + (size_t)dn * 96 + 32 + c);
        float t2 = renc * __ldg(g_lv + (size_t)dn * 96 + 64 + c);

        float y000 = la * renc;
        float y110 = t0 * rs0 + t1 * rs1 + t2 * rs2;
        float u0 = t1 * rs2 - t2 * rs1;
        float u1 = t2 * rs0 - t0 * rs2;
        float u2 = t0 * rs1 - t1 * rs0;

        float4 pa = make_float4(0.f, 0.f, 0.f, 0.f);
        float s000 = 0.f, av0 = 0.f, av1 = 0.f, av2 = 0.f;

#pragma unroll 8
        for (int cc = 0; cc < 32; cc++) {
            float y0 = __shfl_sync(0xffffffffu, y000, cc);
            float y1 = __shfl_sync(0xffffffffu, y110, cc);
            float q0 = __shfl_sync(0xffffffffu, t0, cc);
            float q1 = __shfl_sync(0xffffffffu, t1, cc);
            float q2 = __shfl_sync(0xffffffffu, t2, cc);
            float v0 = __shfl_sync(0xffffffffu, u0, cc);
            float v1 = __shfl_sync(0xffffffffu, u1, cc);
            float v2 = __shfl_sync(0xffffffffu, u2, cc);

            float4 w0 = *(const float4*)&sWy000T[cc * 128 + c * 4];
            float4 w1 = *(const float4*)&sWy110T[cc * 128 + c * 4];
            pa.x += y0 * w0.x + y1 * w1.x;
            pa.y += y0 * w0.y + y1 * w1.y;
            pa.z += y0 * w0.z + y1 * w1.z;
            pa.w += y0 * w0.w + y1 * w1.w;

            float wa = sWy011T[cc * 32 + c];
            float wb = sWy101T[cc * 32 + c];
            float wc = sWy111T[cc * 32 + c];
            s000 += wa * y0;
            av0 += wb * q0 + wc * v0;
            av1 += wb * q1 + wc * v1;
            av2 += wb * q2 + wc * v2;
        }

        *(float4*)(g_psiA0 + (size_t)e * 128 + c * 4) = pa;

        int sn = __ldg(src + e);
        float* bv = Bv + (size_t)sn * 96 + c * 3;
        atomicAdd(bv + 0, 0.1f * (rs0 * s000 + av0));
        atomicAdd(bv + 1, 0.1f * (rs1 * s000 + av1));
        atomicAdd(bv + 2, 0.1f * (rs2 * s000 + av2));
    }
}

// ============================================================
// Kernel 3: fused 3-layer MLP via mma.sync (f16 hi/lo, fp32 acc)
// persistent CTAs, 256 threads, 128-edge tiles, double-buffered W
// smem layout (bytes, halves padded to 136/row = 272B):
//   [0, 34816)           A_hi
//   [34816, 69632)       A_lo
//   [69632 + b*69632 + h*34816)  W buf b, img h
// ============================================================
#define ROWB 272              // bytes per 136-half row
#define A_HI_OFF 0
#define A_LO_OFF 34816
#define W_OFF(b, h) (69632 + (b) * 69632 + (h) * 34816)
#define MLP_DSMEM 208896

__device__ __forceinline__ void stage_W(uint32_t dstHi, uint32_t dstLo, int l, int tid) {
    const uint4* shi = (const uint4*)g_Whl[l][0];
    const uint4* slo = (const uint4*)g_Whl[l][1];
#pragma unroll
    for (int it = 0; it < 8; it++) {
        int i = it * 256 + tid;              // 2048 uint4 per image
        int n = i >> 4, k8 = i & 15;
        uint32_t d = (uint32_t)n * ROWB + k8 * 16;
        CP_ASYNC16(dstHi + d, shi + i);
        CP_ASYNC16(dstLo + d, slo + i);
    }
}

__global__ void __launch_bounds__(256, 1)
mlp_kernel(const float* __restrict__ bm1,
           const float* __restrict__ bm2,
           const int* __restrict__ src,
           float* __restrict__ Ba,
           int n_edges, int ntiles)
{
    extern __shared__ char dsm[];
    __shared__ float s_b[2][128];

    uint32_t sbase = smem_u32(dsm);
    int tid = threadIdx.x;
    int lane = tid & 31, wid = tid >> 5;
    int wm = wid & 3, wn = wid >> 2;          // warp tile: rows wm*32, cols wn*64
    int q = lane & 3, rbase = lane >> 2;

    if (tid < 128) s_b[0][tid] = bm1[tid];
    else s_b[1][tid - 128] = bm2[tid - 128];

    // prefetch W0 into buf 0
    stage_W(sbase + W_OFF(0, 0), sbase + W_OFF(0, 1), 0, tid);
    CP_COMMIT();
    int cur = 0;

    // ldmatrix base addresses (per thread)
    uint32_t aRowHi = sbase + A_HI_OFF + (uint32_t)(wm * 32 + (lane & 15)) * ROWB + ((lane >> 4) << 4);
    uint32_t aRowLo = aRowHi + (A_LO_OFF - A_HI_OFF);
    uint32_t bRow = (uint32_t)(wn * 64 + ((lane >> 4) << 3) + (lane & 7)) * ROWB + (((lane >> 3) & 1) << 4);

    for (int tile = blockIdx.x; tile < ntiles; tile += gridDim.x) {
        // ---- stage A0 from psiA0 (f32 -> hi/lo halves) ----
        const float* at = g_psiA0 + (size_t)tile * 128 * 128;
#pragma unroll
        for (int it = 0; it < 16; it++) {
            int i = it * 256 + tid;           // 4096 float4
            int r = i >> 5, c4 = (i & 31) * 4;
            int e = tile * 128 + r;
            float4 v = make_float4(0.f, 0.f, 0.f, 0.f);
            if (e < n_edges) v = *(const float4*)(at + r * 128 + c4);
            __half h0 = __float2half_rn(v.x), h1 = __float2half_rn(v.y);
            __half h2 = __float2half_rn(v.z), h3 = __float2half_rn(v.w);
            __half l0 = __float2half_rn(v.x - __half2float(h0));
            __half l1 = __float2half_rn(v.y - __half2float(h1));
            __half l2 = __float2half_rn(v.z - __half2float(h2));
            __half l3 = __float2half_rn(v.w - __half2float(h3));
            uint32_t off = (uint32_t)r * ROWB + c4 * 2;
            *(uint2*)(dsm + A_HI_OFF + off) = make_uint2(pack_h2(h0, h1), pack_h2(h2, h3));
            *(uint2*)(dsm + A_LO_OFF + off) = make_uint2(pack_h2(l0, l1), pack_h2(l2, l3));
        }

        for (int l = 0; l < 3; l++) {
            CP_WAIT0();
            __syncthreads();   // W_l ready; A writes (staging or prev epilogue) visible

            // prefetch next W into other buffer
            int nl = (l < 2) ? l + 1 : 0;
            stage_W(sbase + W_OFF(1 - cur, 0), sbase + W_OFF(1 - cur, 1), nl, tid);
            CP_COMMIT();

            uint32_t wHi = sbase + W_OFF(cur, 0);
            uint32_t wLo = sbase + W_OFF(cur, 1);

            float acc[2][8][4];
#pragma unroll
            for (int mf = 0; mf < 2; mf++)
#pragma unroll
                for (int nf = 0; nf < 8; nf++)
#pragma unroll
                    for (int t = 0; t < 4; t++) acc[mf][nf][t] = 0.f;

#pragma unroll
            for (int ks = 0; ks < 8; ks++) {
                uint32_t kb = (uint32_t)ks * 32;   // 16 halves = 32B
                uint32_t ahi[2][4], alo[2][4], bhi[8][2], blo[8][2];
#pragma unroll
                for (int mf = 0; mf < 2; mf++) {
                    ldsm_x4(ahi[mf], aRowHi + (uint32_t)mf * 16 * ROWB + kb);
                    ldsm_x4(alo[mf], aRowLo + (uint32_t)mf * 16 * ROWB + kb);
                }
#pragma unroll
                for (int nf2 = 0; nf2 < 4; nf2++) {
                    uint32_t boff = bRow + (uint32_t)nf2 * 16 * ROWB + kb;
                    ldsm_x4(&bhi[2 * nf2][0], wHi + boff);
                    ldsm_x4(&blo[2 * nf2][0], wLo + boff);
                }
#pragma unroll
                for (int mf = 0; mf < 2; mf++)
#pragma unroll
                    for (int nf = 0; nf < 8; nf++) {
                        mma16816(acc[mf][nf], ahi[mf], bhi[nf]);
                        mma16816(acc[mf][nf], alo[mf], bhi[nf]);
                        mma16816(acc[mf][nf], ahi[mf], blo[nf]);
                    }
            }
            __syncthreads();   // all ldmatrix reads of sA done before overwrite

            if (l < 2) {
                // bias + leaky, split hi/lo, write back to sA
#pragma unroll
                for (int mf = 0; mf < 2; mf++) {
                    int row = wm * 32 + mf * 16 + rbase;
#pragma unroll
                    for (int nf = 0; nf < 8; nf++) {
                        int col = wn * 64 + nf * 8 + 2 * q;
                        float b0 = s_b[l][col], b1 = s_b[l][col + 1];
#pragma unroll
                        for (int h = 0; h < 2; h++) {
                            float x0 = acc[mf][nf][2 * h] + b0;
                            float x1 = acc[mf][nf][2 * h + 1] + b1;
                            x0 = (x0 >= 0.f) ? x0 : 0.1f * x0;
                            x1 = (x1 >= 0.f) ? x1 : 0.1f * x1;
                            __half hh0 = __float2half_rn(x0);
                            __half hh1 = __float2half_rn(x1);
                            __half ll0 = __float2half_rn(x0 - __half2float(hh0));
                            __half ll1 = __float2half_rn(x1 - __half2float(hh1));
                            uint32_t off = (uint32_t)(row + h * 8) * ROWB + col * 2;
                            *(uint32_t*)(dsm + A_HI_OFF + off) = pack_h2(hh0, hh1);
                            *(uint32_t*)(dsm + A_LO_OFF + off) = pack_h2(ll0, ll1);
                        }
                    }
                }
            } else {
                // residual + scale + scatter via vector red
#pragma unroll
                for (int mf = 0; mf < 2; mf++) {
                    int row = wm * 32 + mf * 16 + rbase;
#pragma unroll
                    for (int h = 0; h < 2; h++) {
                        int e = tile * 128 + row + h * 8;
                        if (e >= n_edges) continue;
                        int s = __ldg(src + e);
                        const float* pr = g_psiA0 + (size_t)e * 128;
                        float* bp = Ba + (size_t)s * 128;
#pragma unroll
                        for (int nf = 0; nf < 8; nf++) {
                            int col = wn * 64 + nf * 8 + 2 * q;
                            float2 p = *(const float2*)(pr + col);
                            red_v2(bp + col,
                                   0.1f * (acc[mf][nf][2 * h] + p.x),
                                   0.1f * (acc[mf][nf][2 * h + 1] + p.y));
                        }
                    }
                }
            }
            cur ^= 1;
        }
    }
}

// ============================================================
extern "C" void kernel_launch(void* const* d_in, const int* in_sizes, int n_in,
                              void* d_out, int out_size)
{
    const float* x_a   = (const float*)d_in[0];
    const float* x_v   = (const float*)d_in[1];
    const float* r_ij  = (const float*)d_in[2];
    const int*   src   = (const int*)d_in[3];
    const int*   dst   = (const int*)d_in[4];
    const float* W_L0  = (const float*)d_in[5];
    const float* W_L1  = (const float*)d_in[6];
    const float* W_enc = (const float*)d_in[7];
    const float* b_enc = (const float*)d_in[8];
    const float* Wy000 = (const float*)d_in[9];
    const float* Wy110 = (const float*)d_in[10];
    const float* Wy011 = (const float*)d_in[11];
    const float* Wy101 = (const float*)d_in[12];
    const float* Wy111 = (const float*)d_in[13];
    const float* Wm1   = (const float*)d_in[14];
    const float* bm1   = (const float*)d_in[15];
    const float* Wm2   = (const float*)d_in[16];
    const float* bm2   = (const float*)d_in[17];
    const float* Wm3   = (const float*)d_in[18];

    int n_nodes = in_sizes[0] / 128;
    int n_edges = in_sizes[2] / 3;

    float* Ba = (float*)d_out;
    float* Bv = Ba + (size_t)n_nodes * 128;

    cudaMemsetAsync(d_out, 0, (size_t)out_size * sizeof(float), 0);

    wprep_kernel<<<3, 256>>>(Wm1, Wm2, Wm3);

    node_proj_kernel<<<(n_nodes + 7) / 8, 256>>>(x_a, x_v, W_L0, W_L1, n_nodes);

    edge_kernel<<<(n_edges + 31) / 32, 256>>>(r_ij, src, dst, W_enc, b_enc,
                                              Wy000, Wy110, Wy011, Wy101, Wy111,
                                              Bv, n_edges);

    cudaFuncSetAttribute(mlp_kernel, cudaFuncAttributeMaxDynamicSharedMemorySize, MLP_DSMEM);
    int ntiles = (n_edges + 127) / 128;
    int grid = ntiles < 148 ? ntiles : 148;
    mlp_kernel<<<grid, 256, MLP_DSMEM>>>(bm1, bm2, src, Ba, n_edges, ntiles);
}

// round 9
// speedup vs baseline: 2.9913x; 1.3126x over previous
#include <cuda_runtime.h>
#include <cuda_fp16.h>
#include <math.h>
#include <stdint.h>

#define MAX_NODES 50000
#define MAX_EDGES 500000
#define EPAD (MAX_EDGES + 128)

// ---- scratch (static device globals; no runtime allocation) ----
__device__ float g_la[MAX_NODES * 32];
__device__ float g_lv[MAX_NODES * 96];
__device__ float g_psiA0[(size_t)EPAD * 128];
__device__ __align__(16) __half g_Xh[(size_t)EPAD * 256];
__device__ __align__(16) __half g_Xl[(size_t)EPAD * 256];
__device__ float4 g_rs4[EPAD];
// weight images: [0]=combined front (Wc0|Wy011|WcV), [1..3]=Wm1..3; hi/lo
__device__ __align__(16) __half g_Whl[4][2][128 * 128];

// ============================================================
// helpers
// ============================================================
__device__ __forceinline__ uint32_t smem_u32(const void* p) {
    uint32_t a;
    asm("{ .reg .u64 t; cvta.to.shared.u64 t, %1; cvt.u32.u64 %0, t; }" : "=r"(a) : "l"(p));
    return a;
}
__device__ __forceinline__ void ldsm_x4(uint32_t r[4], uint32_t addr) {
    asm volatile("ldmatrix.sync.aligned.m8n8.x4.shared.b16 {%0,%1,%2,%3}, [%4];"
                 : "=r"(r[0]), "=r"(r[1]), "=r"(r[2]), "=r"(r[3]) : "r"(addr));
}
__device__ __forceinline__ void mma16816(float c[4], const uint32_t a[4], const uint32_t b[2]) {
    asm volatile("mma.sync.aligned.m16n8k16.row.col.f32.f16.f16.f32 "
                 "{%0,%1,%2,%3}, {%4,%5,%6,%7}, {%8,%9}, {%0,%1,%2,%3};"
                 : "+f"(c[0]), "+f"(c[1]), "+f"(c[2]), "+f"(c[3])
                 : "r"(a[0]), "r"(a[1]), "r"(a[2]), "r"(a[3]), "r"(b[0]), "r"(b[1]));
}
#define CP_ASYNC16(dst, src) \
    asm volatile("cp.async.cg.shared.global [%0], [%1], 16;" :: "r"(dst), "l"(src) : "memory")
#define CP_COMMIT() asm volatile("cp.async.commit_group;" ::: "memory")
#define CP_WAIT0()  asm volatile("cp.async.wait_group 0;" ::: "memory")
#define CP_WAIT1()  asm volatile("cp.async.wait_group 1;" ::: "memory")

__device__ __forceinline__ void red_v2(float* p, float a, float b) {
    asm volatile("red.global.add.v2.f32 [%0], {%1,%2};" :: "l"(p), "f"(a), "f"(b) : "memory");
}
__device__ __forceinline__ void red_f32(float* p, float a) {
    asm volatile("red.global.add.f32 [%0], %1;" :: "l"(p), "f"(a) : "memory");
}
__device__ __forceinline__ uint32_t pack_h2(__half a, __half b) {
    __half2 t = __halves2half2(a, b);
    return *reinterpret_cast<uint32_t*>(&t);
}

// ============================================================
// Kernel 0: weight prep
// layer 0 image: k<64: [Wy000|Wy110]; rows 64..95,k 64..95: Wy011;
// rows 96..127, k 64..127: [Wy101|Wy111]; else 0.
// ============================================================
__global__ void wprep_kernel(const float* __restrict__ W1,
                             const float* __restrict__ W2,
                             const float* __restrict__ W3,
                             const float* __restrict__ Wy000,
                             const float* __restrict__ Wy110,
                             const float* __restrict__ Wy011,
                             const float* __restrict__ Wy101,
                             const float* __restrict__ Wy111)
{
    int L = blockIdx.x;
    for (int idx = threadIdx.x; idx < 128 * 128; idx += blockDim.x) {
        int n = idx >> 7, k = idx & 127;
        float wv = 0.f;
        if (L == 0) {
            if (k < 64) wv = (k < 32) ? Wy000[n * 32 + k] : Wy110[n * 32 + k - 32];
            else if (n >= 64 && n < 96 && k < 96) wv = Wy011[(n - 64) * 32 + (k - 64)];
            else if (n >= 96) wv = (k < 96) ? Wy101[(n - 96) * 32 + (k - 64)]
                                            : Wy111[(n - 96) * 32 + (k - 96)];
        } else {
            const float* Ws = (L == 1) ? W1 : (L == 2) ? W2 : W3;
            wv = Ws[idx];
        }
        __half hi = __float2half_rn(wv);
        __half lo = __float2half_rn(wv - __half2float(hi));
        g_Whl[L][0][idx] = hi;
        g_Whl[L][1][idx] = lo;
    }
}

// ============================================================
// Kernel 1: node projections (unchanged)
// ============================================================
__global__ void node_proj_kernel(const float* __restrict__ x_a,
                                 const float* __restrict__ x_v,
                                 const float* __restrict__ W_L0,
                                 const float* __restrict__ W_L1,
                                 int n_nodes)
{
    __shared__ float sWL0T[128 * 32];
    __shared__ float sWL1T[32 * 32];
    __shared__ float sxa[8][128];
    __shared__ float sxv[8][96];

    int tid = threadIdx.x;
    for (int idx = tid; idx < 4096; idx += 256) { int c = idx >> 7, d = idx & 127; sWL0T[d * 32 + c] = W_L0[idx]; }
    for (int idx = tid; idx < 1024; idx += 256) { int c = idx >> 5, d = idx & 31;  sWL1T[d * 32 + c] = W_L1[idx]; }
    __syncthreads();

    int w = tid >> 5, c = tid & 31;
    int node = blockIdx.x * 8 + w;
    if (node >= n_nodes) return;

    *(float4*)&sxa[w][c * 4] = *(const float4*)(x_a + (size_t)node * 128 + c * 4);
    if (c < 24) *(float4*)&sxv[w][c * 4] = *(const float4*)(x_v + (size_t)node * 96 + c * 4);
    __syncwarp();

    float la = 0.f;
#pragma unroll 8
    for (int d = 0; d < 128; d++) la += sxa[w][d] * sWL0T[d * 32 + c];

    float lv0 = 0.f, lv1 = 0.f, lv2 = 0.f;
#pragma unroll 8
    for (int d = 0; d < 32; d++) {
        float wl = sWL1T[d * 32 + c];
        lv0 += sxv[w][d * 3 + 0] * wl;
        lv1 += sxv[w][d * 3 + 1] * wl;
        lv2 += sxv[w][d * 3 + 2] * wl;
    }
    g_la[node * 32 + c] = la;
    g_lv[node * 96 + 0 + c]  = lv0;
    g_lv[node * 96 + 32 + c] = lv1;
    g_lv[node * 96 + 64 + c] = lv2;
}

// ============================================================
// Kernel 2: per-edge elementwise only — writes X rows (hi/lo f16) + rs
// X col blocks: 0=y000 1=y110 2=t0 3=u0 4=t1 5=u1 6=t2 7=u2 (32 chans each)
// ============================================================
__global__ void edge_kernel(const float* __restrict__ r_ij,
                            const int* __restrict__ dst,
                            const float* __restrict__ W_enc,
                            const float* __restrict__ b_enc,
                            int n_edges)
{
    __shared__ float sWencT[8 * 32];
    __shared__ float sbenc[32];
    int tid = threadIdx.x;
    if (tid < 256) { int cch = tid >> 3, k = tid & 7; sWencT[k * 32 + cch] = W_enc[tid]; }
    if (tid < 32) sbenc[tid] = b_enc[tid];
    __syncthreads();

    int w = tid >> 5, c = tid & 31;

#pragma unroll
    for (int ei = 0; ei < 4; ei++) {
        int e = blockIdx.x * 32 + ei * 8 + w;
        if (e >= n_edges) continue;

        float r0 = __ldg(r_ij + (size_t)e * 3 + 0);
        float r1 = __ldg(r_ij + (size_t)e * 3 + 1);
        float r2 = __ldg(r_ij + (size_t)e * 3 + 2);
        float rr = sqrtf(r0 * r0 + r1 * r1 + r2 * r2);

        float ex = 0.f;
        if (c < 8) {
            float ctr = (5.0f / 7.0f) * (float)c;
            float dd = (rr - ctr) * (8.0f / 5.0f);
            ex = expf(-dd * dd);
        }
        float renc = sbenc[c];
#pragma unroll
        for (int k = 0; k < 8; k++)
            renc += __shfl_sync(0xffffffffu, ex, k) * sWencT[k * 32 + c];

        float nn = 1.4f * rr;
        float th = tanhf(nn) / fmaxf(nn, 1e-6f);
        float rs0 = 1.4f * r0 * th, rs1 = 1.4f * r1 * th, rs2 = 1.4f * r2 * th;

        int dn = __ldg(dst + e);
        float la = __ldg(g_la + (size_t)dn * 32 + c);
        float t0 = renc * __ldg(g_lv + (size_t)dn * 96 + 0 + c);
        float t1 = renc * __ldg(g_lv + (size_t)dn * 96 + 32 + c);
        float t2 = renc * __ldg(g_lv + (size_t)dn * 96 + 64 + c);

        float y000 = la * renc;
        float y110 = t0 * rs0 + t1 * rs1 + t2 * rs2;
        float u0 = t1 * rs2 - t2 * rs1;
        float u1 = t2 * rs0 - t0 * rs2;
        float u2 = t0 * rs1 - t1 * rs0;

        if (c == 0) g_rs4[e] = make_float4(rs0, rs1, rs2, 0.f);

        float vals[8] = {y000, y110, t0, u0, t1, u1, t2, u2};
        size_t xb = (size_t)e * 256 + c;
#pragma unroll
        for (int j = 0; j < 8; j++) {
            float v = vals[j];
            __half h = __float2half_rn(v);
            __half l = __float2half_rn(v - __half2float(h));
            g_Xh[xb + j * 32] = h;
            g_Xl[xb + j * 32] = l;
        }
    }
}

// ============================================================
// Kernel 3: fused front-GEMMs + 3-layer MLP via mma.sync
// ============================================================
#define ROWB 272
#define A_HI_OFF 0
#define A_LO_OFF 34816
#define W_OFF(b, h) (69632 + (b) * 69632 + (h) * 34816)
#define P_OFF 208896
#define RS_OFF 225792
#define SRC_OFF 227840
#define MLP_DSMEM 228352

__device__ __forceinline__ void stage_W(uint32_t dstHi, uint32_t dstLo, int l, int tid) {
    const uint4* shi = (const uint4*)g_Whl[l][0];
    const uint4* slo = (const uint4*)g_Whl[l][1];
#pragma unroll
    for (int it = 0; it < 8; it++) {
        int i = it * 256 + tid;
        int n = i >> 4, k8 = i & 15;
        uint32_t d = (uint32_t)n * ROWB + k8 * 16;
        CP_ASYNC16(dstHi + d, shi + i);
        CP_ASYNC16(dstLo + d, slo + i);
    }
}

__device__ __forceinline__ void stage_X(uint32_t sbase, int tile, int half, int tid) {
    const uint32_t* xh = (const uint32_t*)g_Xh + (size_t)tile * 128 * 128 + half * 64;
    const uint32_t* xl = (const uint32_t*)g_Xl + (size_t)tile * 128 * 128 + half * 64;
#pragma unroll
    for (int it = 0; it < 8; it++) {
        int i = it * 256 + tid;
        int r = i >> 4, k16 = i & 15;
        uint32_t d = (uint32_t)r * ROWB + k16 * 16;
        CP_ASYNC16(sbase + A_HI_OFF + d, xh + (size_t)r * 128 + k16 * 4);
        CP_ASYNC16(sbase + A_LO_OFF + d, xl + (size_t)r * 128 + k16 * 4);
    }
}

template <int K0, int K1>
__device__ __forceinline__ void layer_mma(float acc[2][8][4], uint32_t aHi, uint32_t aLo,
                                          uint32_t wHi, uint32_t wLo, uint32_t bRow)
{
#pragma unroll
    for (int ks = K0; ks < K1; ks++) {
        uint32_t kb = (uint32_t)ks * 32;
        uint32_t ahi[2][4], alo[2][4], bhi[8][2], blo[8][2];
#pragma unroll
        for (int mf = 0; mf < 2; mf++) {
            ldsm_x4(ahi[mf], aHi + (uint32_t)mf * 16 * ROWB + kb);
            ldsm_x4(alo[mf], aLo + (uint32_t)mf * 16 * ROWB + kb);
        }
#pragma unroll
        for (int nf2 = 0; nf2 < 4; nf2++) {
            ldsm_x4(&bhi[2 * nf2][0], wHi + bRow + (uint32_t)nf2 * 16 * ROWB + kb);
            ldsm_x4(&blo[2 * nf2][0], wLo + bRow + (uint32_t)nf2 * 16 * ROWB + kb);
        }
#pragma unroll
        for (int mf = 0; mf < 2; mf++)
#pragma unroll
            for (int nf = 0; nf < 8; nf++) {
                mma16816(acc[mf][nf], ahi[mf], bhi[nf]);
                mma16816(acc[mf][nf], alo[mf], bhi[nf]);
                mma16816(acc[mf][nf], ahi[mf], blo[nf]);
            }
    }
}

// N=32 GEMM, 16-row A tile per warp
template <int K0, int K1>
__device__ __forceinline__ void small_mma(float acc[4][4], uint32_t aHi, uint32_t aLo,
                                          uint32_t wHi, uint32_t wLo, uint32_t bRowS)
{
#pragma unroll
    for (int ks = K0; ks < K1; ks++) {
        uint32_t akb = (uint32_t)ks * 32, bkb = (uint32_t)(ks - K0) * 32;
        uint32_t ah[4], al[4], bh[8], bl[8];
        ldsm_x4(ah, aHi + akb);
        ldsm_x4(al, aLo + akb);
#pragma unroll
        for (int nf2 = 0; nf2 < 2; nf2++) {
            ldsm_x4(&bh[4 * nf2], wHi + bRowS + (uint32_t)nf2 * 16 * ROWB + bkb);
            ldsm_x4(&bl[4 * nf2], wLo + bRowS + (uint32_t)nf2 * 16 * ROWB + bkb);
        }
#pragma unroll
        for (int nf = 0; nf < 4; nf++) {
            mma16816(acc[nf], ah, &bh[2 * nf]);
            mma16816(acc[nf], al, &bh[2 * nf]);
            mma16816(acc[nf], ah, &bl[2 * nf]);
        }
    }
}

__global__ void __launch_bounds__(256, 1)
mlp_kernel(const float* __restrict__ bm1,
           const float* __restrict__ bm2,
           const int* __restrict__ src,
           float* __restrict__ Ba,
           float* __restrict__ Bv,
           int n_edges, int ntiles)
{
    extern __shared__ char dsm[];
    __shared__ float s_b[2][128];

    uint32_t sbase = smem_u32(dsm);
    int tid = threadIdx.x;
    int lane = tid & 31, wid = tid >> 5;
    int wm = wid & 3, wn = wid >> 2;
    int q = lane & 3, rbase = lane >> 2;

    if (tid < 128) s_b[0][tid] = bm1[tid];
    else s_b[1][tid - 128] = bm2[tid - 128];

    uint32_t aRowHi = sbase + A_HI_OFF + (uint32_t)(wm * 32 + (lane & 15)) * ROWB + ((lane >> 4) << 4);
    uint32_t aRowLo = aRowHi + (A_LO_OFF - A_HI_OFF);
    uint32_t aRow16 = sbase + A_HI_OFF + (uint32_t)(wid * 16 + (lane & 15)) * ROWB + ((lane >> 4) << 4);
    uint32_t aRow16Lo = aRow16 + (A_LO_OFF - A_HI_OFF);
    uint32_t bRow  = (uint32_t)(wn * 64 + ((lane >> 4) << 3) + (lane & 7)) * ROWB + (((lane >> 3) & 1) << 4);
    uint32_t bRowP = (uint32_t)(64 + ((lane >> 4) << 3) + (lane & 7)) * ROWB + (((lane >> 3) & 1) << 4) + 128;
    uint32_t bRowV = (uint32_t)(96 + ((lane >> 4) << 3) + (lane & 7)) * ROWB + (((lane >> 3) & 1) << 4) + 128;

    float* p_slab = (float*)(dsm + P_OFF);
    float4* srs = (float4*)(dsm + RS_OFF);
    int* ssrc = (int*)(dsm + SRC_OFF);

    // preload front weight image into buf0
    stage_W(sbase + W_OFF(0, 0), sbase + W_OFF(0, 1), 0, tid); CP_COMMIT();

    for (int tile = blockIdx.x; tile < ntiles; tile += gridDim.x) {
        stage_X(sbase, tile, 0, tid); CP_COMMIT();
        stage_W(sbase + W_OFF(1, 0), sbase + W_OFF(1, 1), 1, tid); CP_COMMIT();
        if (tid < 128) {
            int e = tile * 128 + tid;
            ssrc[tid] = (e < n_edges) ? src[e] : 0;
            srs[tid] = (e < n_edges) ? g_rs4[e] : make_float4(0.f, 0.f, 0.f, 0.f);
        }
        CP_WAIT1();           // front-W(prev) + Xa1 done; Wm1 may be pending
        __syncthreads();

        // ---- front MMA set 1: psi_a0, p, pv0 (A = [y000|y110|t0|u0]) ----
        float acc_a[2][8][4];
#pragma unroll
        for (int mf = 0; mf < 2; mf++)
#pragma unroll
            for (int nf = 0; nf < 8; nf++)
#pragma unroll
                for (int t = 0; t < 4; t++) acc_a[mf][nf][t] = 0.f;
        layer_mma<0, 4>(acc_a, aRowHi, aRowLo, sbase + W_OFF(0, 0), sbase + W_OFF(0, 1), bRow);

        float acc_p[4][4], acc_v0[4][4];
#pragma unroll
        for (int nf = 0; nf < 4; nf++)
#pragma unroll
            for (int t = 0; t < 4; t++) { acc_p[nf][t] = 0.f; acc_v0[nf][t] = 0.f; }
        small_mma<0, 2>(acc_p, aRow16, aRow16Lo, sbase + W_OFF(0, 0), sbase + W_OFF(0, 1), bRowP);
        small_mma<4, 8>(acc_v0, aRow16, aRow16Lo, sbase + W_OFF(0, 0), sbase + W_OFF(0, 1), bRowV);
        __syncthreads();      // all A / Ws1 reads done

        stage_X(sbase, tile, 1, tid); CP_COMMIT();   // Xa2 = [t1|u1|t2|u2]

        // psi_a0 -> global, p -> smem
#pragma unroll
        for (int mf = 0; mf < 2; mf++) {
            int row0 = wm * 32 + mf * 16 + rbase;
#pragma unroll
            for (int nf = 0; nf < 8; nf++) {
                int col = wn * 64 + nf * 8 + 2 * q;
                float* dp = g_psiA0 + (size_t)(tile * 128 + row0) * 128 + col;
                *(float2*)dp = make_float2(acc_a[mf][nf][0], acc_a[mf][nf][1]);
                *(float2*)(dp + 8 * 128) = make_float2(acc_a[mf][nf][2], acc_a[mf][nf][3]);
            }
        }
        {
            int row = wid * 16 + rbase;
#pragma unroll
            for (int nf = 0; nf < 4; nf++) {
                int col = nf * 8 + 2 * q;
                p_slab[row * 33 + col] = acc_p[nf][0];
                p_slab[row * 33 + col + 1] = acc_p[nf][1];
                p_slab[(row + 8) * 33 + col] = acc_p[nf][2];
                p_slab[(row + 8) * 33 + col + 1] = acc_p[nf][3];
            }
        }
        __syncthreads();      // p visible

        // pv0 epilogue
#pragma unroll
        for (int nf = 0; nf < 4; nf++) {
            int col = nf * 8 + 2 * q;
#pragma unroll
            for (int h = 0; h < 2; h++) {
                int row = wid * 16 + rbase + h * 8;
                int e = tile * 128 + row;
                if (e >= n_edges) continue;
                float rsv = srs[row].x;
                int s = ssrc[row];
                float v0 = 0.1f * (acc_v0[nf][2 * h] + p_slab[row * 33 + col] * rsv);
                float v1 = 0.1f * (acc_v0[nf][2 * h + 1] + p_slab[row * 33 + col + 1] * rsv);
                red_f32(Bv + (size_t)s * 96 + col * 3, v0);
                red_f32(Bv + (size_t)s * 96 + (col + 1) * 3, v1);
            }
        }

        CP_WAIT0();           // Xa2 (and Wm1) done
        __syncthreads();

        // ---- front MMA set 2: pv1, pv2 ----
        float acc_v1[4][4], acc_v2[4][4];
#pragma unroll
        for (int nf = 0; nf < 4; nf++)
#pragma unroll
            for (int t = 0; t < 4; t++) { acc_v1[nf][t] = 0.f; acc_v2[nf][t] = 0.f; }
        small_mma<0, 4>(acc_v1, aRow16, aRow16Lo, sbase + W_OFF(0, 0), sbase + W_OFF(0, 1), bRowV);
        small_mma<4, 8>(acc_v2, aRow16, aRow16Lo, sbase + W_OFF(0, 0), sbase + W_OFF(0, 1), bRowV);
        __syncthreads();      // A + Ws1 reads done

        // stage psi_a0 -> A (f32 -> hi/lo)
        {
            const float* at = g_psiA0 + (size_t)tile * 128 * 128;
#pragma unroll
            for (int it = 0; it < 16; it++) {
                int i = it * 256 + tid;
                int r = i >> 5, c4 = (i & 31) * 4;
                float4 v = *(const float4*)(at + r * 128 + c4);
                __half h0 = __float2half_rn(v.x), h1 = __float2half_rn(v.y);
                __half h2 = __float2half_rn(v.z), h3 = __float2half_rn(v.w);
                __half l0 = __float2half_rn(v.x - __half2float(h0));
                __half l1 = __float2half_rn(v.y - __half2float(h1));
                __half l2 = __float2half_rn(v.z - __half2float(h2));
                __half l3 = __float2half_rn(v.w - __half2float(h3));
                uint32_t off = (uint32_t)r * ROWB + c4 * 2;
                *(uint2*)(dsm + A_HI_OFF + off) = make_uint2(pack_h2(h0, h1), pack_h2(h2, h3));
                *(uint2*)(dsm + A_LO_OFF + off) = make_uint2(pack_h2(l0, l1), pack_h2(l2, l3));
            }
        }
        // pv1 / pv2 epilogues
#pragma unroll
        for (int comp = 1; comp < 3; comp++) {
            float (*av)[4] = (comp == 1) ? acc_v1 : acc_v2;
#pragma unroll
            for (int nf = 0; nf < 4; nf++) {
                int col = nf * 8 + 2 * q;
#pragma unroll
                for (int h = 0; h < 2; h++) {
                    int row = wid * 16 + rbase + h * 8;
                    int e = tile * 128 + row;
                    if (e >= n_edges) continue;
                    float rsv = (comp == 1) ? srs[row].y : srs[row].z;
                    int s = ssrc[row];
                    float v0 = 0.1f * (av[nf][2 * h] + p_slab[row * 33 + col] * rsv);
                    float v1 = 0.1f * (av[nf][2 * h + 1] + p_slab[row * 33 + col + 1] * rsv);
                    red_f32(Bv + (size_t)s * 96 + col * 3 + comp, v0);
                    red_f32(Bv + (size_t)s * 96 + (col + 1) * 3 + comp, v1);
                }
            }
        }
        __syncthreads();      // A ready for S2

        // ---- S2 (Wm1 in buf1) ----
        stage_W(sbase + W_OFF(0, 0), sbase + W_OFF(0, 1), 2, tid); CP_COMMIT();  // Wm2 -> buf0
        float acc[2][8][4];
#pragma unroll
        for (int mf = 0; mf < 2; mf++)
#pragma unroll
            for (int nf = 0; nf < 8; nf++)
#pragma unroll
                for (int t = 0; t < 4; t++) acc[mf][nf][t] = 0.f;
        layer_mma<0, 8>(acc, aRowHi, aRowLo, sbase + W_OFF(1, 0), sbase + W_OFF(1, 1), bRow);
        __syncthreads();
#pragma unroll
        for (int mf = 0; mf < 2; mf++) {
            int row = wm * 32 + mf * 16 + rbase;
#pragma unroll
            for (int nf = 0; nf < 8; nf++) {
                int col = wn * 64 + nf * 8 + 2 * q;
                float b0 = s_b[0][col], b1 = s_b[0][col + 1];
#pragma unroll
                for (int h = 0; h < 2; h++) {
                    float x0 = acc[mf][nf][2 * h] + b0;
                    float x1 = acc[mf][nf][2 * h + 1] + b1;
                    x0 = (x0 >= 0.f) ? x0 : 0.1f * x0;
                    x1 = (x1 >= 0.f) ? x1 : 0.1f * x1;
                    __half hh0 = __float2half_rn(x0), hh1 = __float2half_rn(x1);
                    __half ll0 = __float2half_rn(x0 - __half2float(hh0));
                    __half ll1 = __float2half_rn(x1 - __half2float(hh1));
                    uint32_t off = (uint32_t)(row + h * 8) * ROWB + col * 2;
                    *(uint32_t*)(dsm + A_HI_OFF + off) = pack_h2(hh0, hh1);
                    *(uint32_t*)(dsm + A_LO_OFF + off) = pack_h2(ll0, ll1);
                }
            }
        }
        __syncthreads();
        CP_WAIT0();           // Wm2 ready

        // ---- S3 (Wm2 in buf0) ----
        stage_W(sbase + W_OFF(1, 0), sbase + W_OFF(1, 1), 3, tid); CP_COMMIT();  // Wm3 -> buf1
#pragma unroll
        for (int mf = 0; mf < 2; mf++)
#pragma unroll
            for (int nf = 0; nf < 8; nf++)
#pragma unroll
                for (int t = 0; t < 4; t++) acc[mf][nf][t] = 0.f;
        layer_mma<0, 8>(acc, aRowHi, aRowLo, sbase + W_OFF(0, 0), sbase + W_OFF(0, 1), bRow);
        __syncthreads();
#pragma unroll
        for (int mf = 0; mf < 2; mf++) {
            int row = wm * 32 + mf * 16 + rbase;
#pragma unroll
            for (int nf = 0; nf < 8; nf++) {
                int col = wn * 64 + nf * 8 + 2 * q;
                float b0 = s_b[1][col], b1 = s_b[1][col + 1];
#pragma unroll
                for (int h = 0; h < 2; h++) {
                    float x0 = acc[mf][nf][2 * h] + b0;
                    float x1 = acc[mf][nf][2 * h + 1] + b1;
                    x0 = (x0 >= 0.f) ? x0 : 0.1f * x0;
                    x1 = (x1 >= 0.f) ? x1 : 0.1f * x1;
                    __half hh0 = __float2half_rn(x0), hh1 = __float2half_rn(x1);
                    __half ll0 = __float2half_rn(x0 - __half2float(hh0));
                    __half ll1 = __float2half_rn(x1 - __half2float(hh1));
                    uint32_t off = (uint32_t)(row + h * 8) * ROWB + col * 2;
                    *(uint32_t*)(dsm + A_HI_OFF + off) = pack_h2(hh0, hh1);
                    *(uint32_t*)(dsm + A_LO_OFF + off) = pack_h2(ll0, ll1);
                }
            }
        }
        __syncthreads();
        CP_WAIT0();           // Wm3 ready

        // ---- S4 (Wm3 in buf1) ----
        stage_W(sbase + W_OFF(0, 0), sbase + W_OFF(0, 1), 0, tid); CP_COMMIT();  // Ws1 -> buf0 (next tile)
#pragma unroll
        for (int mf = 0; mf < 2; mf++)
#pragma unroll
            for (int nf = 0; nf < 8; nf++)
#pragma unroll
                for (int t = 0; t < 4; t++) acc[mf][nf][t] = 0.f;
        layer_mma<0, 8>(acc, aRowHi, aRowLo, sbase + W_OFF(1, 0), sbase + W_OFF(1, 1), bRow);

        // residual + scale + scatter
#pragma unroll
        for (int mf = 0; mf < 2; mf++) {
            int row0 = wm * 32 + mf * 16 + rbase;
#pragma unroll
            for (int h = 0; h < 2; h++) {
                int row = row0 + h * 8;
                int e = tile * 128 + row;
                if (e >= n_edges) continue;
                int s = ssrc[row];
                const float* pr = g_psiA0 + (size_t)e * 128;
                float* bp = Ba + (size_t)s * 128;
#pragma unroll
                for (int nf = 0; nf < 8; nf++) {
                    int col = wn * 64 + nf * 8 + 2 * q;
                    float2 p = *(const float2*)(pr + col);
                    red_v2(bp + col,
                           0.1f * (acc[mf][nf][2 * h] + p.x),
                           0.1f * (acc[mf][nf][2 * h + 1] + p.y));
                }
            }
        }
        __syncthreads();      // protect A before next tile's stage_X
    }
}

// ============================================================
extern "C" void kernel_launch(void* const* d_in, const int* in_sizes, int n_in,
                              void* d_out, int out_size)
{
    const float* x_a   = (const float*)d_in[0];
    const float* x_v   = (const float*)d_in[1];
    const float* r_ij  = (const float*)d_in[2];
    const int*   src   = (const int*)d_in[3];
    const int*   dst   = (const int*)d_in[4];
    const float* W_L0  = (const float*)d_in[5];
    const float* W_L1  = (const float*)d_in[6];
    const float* W_enc = (const float*)d_in[7];
    const float* b_enc = (const float*)d_in[8];
    const float* Wy000 = (const float*)d_in[9];
    const float* Wy110 = (const float*)d_in[10];
    const float* Wy011 = (const float*)d_in[11];
    const float* Wy101 = (const float*)d_in[12];
    const float* Wy111 = (const float*)d_in[13];
    const float* Wm1   = (const float*)d_in[14];
    const float* bm1   = (const float*)d_in[15];
    const float* Wm2   = (const float*)d_in[16];
    const float* bm2   = (const float*)d_in[17];
    const float* Wm3   = (const float*)d_in[18];

    int n_nodes = in_sizes[0] / 128;
    int n_edges = in_sizes[2] / 3;

    float* Ba = (float*)d_out;
    float* Bv = Ba + (size_t)n_nodes * 128;

    cudaMemsetAsync(d_out, 0, (size_t)out_size * sizeof(float), 0);

    wprep_kernel<<<4, 256>>>(Wm1, Wm2, Wm3, Wy000, Wy110, Wy011, Wy101, Wy111);

    node_proj_kernel<<<(n_nodes + 7) / 8, 256>>>(x_a, x_v, W_L0, W_L1, n_nodes);

    edge_kernel<<<(n_edges + 31) / 32, 256>>>(r_ij, dst, W_enc, b_enc, n_edges);

    cudaFuncSetAttribute(mlp_kernel, cudaFuncAttributeMaxDynamicSharedMemorySize, MLP_DSMEM);
    int ntiles = (n_edges + 127) / 128;
    int grid = ntiles < 148 ? ntiles : 148;
    mlp_kernel<<<grid, 256, MLP_DSMEM>>>(bm1, bm2, src, Ba, Bv, n_edges, ntiles);
}

// round 13
// speedup vs baseline: 3.5044x; 1.1715x over previous
#include <cuda_runtime.h>
#include <cuda_fp16.h>
#include <math.h>
#include <stdint.h>

#define MAX_NODES 50000
#define MAX_EDGES 500000
#define EPAD (MAX_EDGES + 128)

// ---- scratch (static device globals; no runtime allocation) ----
__device__ float g_la[MAX_NODES * 32];
__device__ float g_lv[MAX_NODES * 96];
__device__ __align__(16) __half g_Xh[(size_t)EPAD * 256];
__device__ __align__(16) __half g_Xl[(size_t)EPAD * 256];
__device__ float4 g_rs4[EPAD];
// weight images: [0]=combined front (Wc0|Wy011|WcV), [1..3]=Wm1..3; hi/lo
__device__ __align__(16) __half g_Whl[4][2][128 * 128];

// ============================================================
// helpers
// ============================================================
__device__ __forceinline__ uint32_t smem_u32(const void* p) {
    uint32_t a;
    asm("{ .reg .u64 t; cvta.to.shared.u64 t, %1; cvt.u32.u64 %0, t; }" : "=r"(a) : "l"(p));
    return a;
}
__device__ __forceinline__ void ldsm_x4(uint32_t r[4], uint32_t addr) {
    asm volatile("ldmatrix.sync.aligned.m8n8.x4.shared.b16 {%0,%1,%2,%3}, [%4];"
                 : "=r"(r[0]), "=r"(r[1]), "=r"(r[2]), "=r"(r[3]) : "r"(addr));
}
__device__ __forceinline__ void mma16816(float c[4], const uint32_t a[4], const uint32_t b[2]) {
    asm volatile("mma.sync.aligned.m16n8k16.row.col.f32.f16.f16.f32 "
                 "{%0,%1,%2,%3}, {%4,%5,%6,%7}, {%8,%9}, {%0,%1,%2,%3};"
                 : "+f"(c[0]), "+f"(c[1]), "+f"(c[2]), "+f"(c[3])
                 : "r"(a[0]), "r"(a[1]), "r"(a[2]), "r"(a[3]), "r"(b[0]), "r"(b[1]));
}
#define CP_ASYNC16(dst, src) \
    asm volatile("cp.async.cg.shared.global [%0], [%1], 16;" :: "r"(dst), "l"(src) : "memory")
#define CP_COMMIT() asm volatile("cp.async.commit_group;" ::: "memory")
#define CP_WAIT0()  asm volatile("cp.async.wait_group 0;" ::: "memory")

__device__ __forceinline__ void red_v2(float* p, float a, float b) {
    asm volatile("red.global.add.v2.f32 [%0], {%1,%2};" :: "l"(p), "f"(a), "f"(b) : "memory");
}
__device__ __forceinline__ void red_f32(float* p, float a) {
    asm volatile("red.global.add.f32 [%0], %1;" :: "l"(p), "f"(a) : "memory");
}
__device__ __forceinline__ uint32_t pack_h2(__half a, __half b) {
    __half2 t = __halves2half2(a, b);
    return *reinterpret_cast<uint32_t*>(&t);
}

// ============================================================
// Kernel 0: weight prep
// layer 0 image: k<64: [Wy000|Wy110]; rows 64..95,k 64..95: Wy011;
// rows 96..127, k 64..127: [Wy101|Wy111]; else 0.
// ============================================================
__global__ void wprep_kernel(const float* __restrict__ W1,
                             const float* __restrict__ W2,
                             const float* __restrict__ W3,
                             const float* __restrict__ Wy000,
                             const float* __restrict__ Wy110,
                             const float* __restrict__ Wy011,
                             const float* __restrict__ Wy101,
                             const float* __restrict__ Wy111)
{
    int L = blockIdx.x;
    for (int idx = threadIdx.x; idx < 128 * 128; idx += blockDim.x) {
        int n = idx >> 7, k = idx & 127;
        float wv = 0.f;
        if (L == 0) {
            if (k < 64) wv = (k < 32) ? Wy000[n * 32 + k] : Wy110[n * 32 + k - 32];
            else if (n >= 64 && n < 96 && k < 96) wv = Wy011[(n - 64) * 32 + (k - 64)];
            else if (n >= 96) wv = (k < 96) ? Wy101[(n - 96) * 32 + (k - 64)]
                                            : Wy111[(n - 96) * 32 + (k - 96)];
        } else {
            const float* Ws = (L == 1) ? W1 : (L == 2) ? W2 : W3;
            wv = Ws[idx];
        }
        __half hi = __float2half_rn(wv);
        __half lo = __float2half_rn(wv - __half2float(hi));
        g_Whl[L][0][idx] = hi;
        g_Whl[L][1][idx] = lo;
    }
}

// ============================================================
// Kernel 1: node projections
// ============================================================
__global__ void node_proj_kernel(const float* __restrict__ x_a,
                                 const float* __restrict__ x_v,
                                 const float* __restrict__ W_L0,
                                 const float* __restrict__ W_L1,
                                 int n_nodes)
{
    __shared__ float sWL0T[128 * 32];
    __shared__ float sWL1T[32 * 32];
    __shared__ float sxa[8][128];
    __shared__ float sxv[8][96];

    int tid = threadIdx.x;
    for (int idx = tid; idx < 4096; idx += 256) { int c = idx >> 7, d = idx & 127; sWL0T[d * 32 + c] = W_L0[idx]; }
    for (int idx = tid; idx < 1024; idx += 256) { int c = idx >> 5, d = idx & 31;  sWL1T[d * 32 + c] = W_L1[idx]; }
    __syncthreads();

    int w = tid >> 5, c = tid & 31;
    int node = blockIdx.x * 8 + w;
    if (node >= n_nodes) return;

    *(float4*)&sxa[w][c * 4] = *(const float4*)(x_a + (size_t)node * 128 + c * 4);
    if (c < 24) *(float4*)&sxv[w][c * 4] = *(const float4*)(x_v + (size_t)node * 96 + c * 4);
    __syncwarp();

    float la = 0.f;
#pragma unroll 8
    for (int d = 0; d < 128; d++) la += sxa[w][d] * sWL0T[d * 32 + c];

    float lv0 = 0.f, lv1 = 0.f, lv2 = 0.f;
#pragma unroll 8
    for (int d = 0; d < 32; d++) {
        float wl = sWL1T[d * 32 + c];
        lv0 += sxv[w][d * 3 + 0] * wl;
        lv1 += sxv[w][d * 3 + 1] * wl;
        lv2 += sxv[w][d * 3 + 2] * wl;
    }
    g_la[node * 32 + c] = la;
    g_lv[node * 96 + 0 + c]  = lv0;
    g_lv[node * 96 + 32 + c] = lv1;
    g_lv[node * 96 + 64 + c] = lv2;
}

// ============================================================
// Kernel 2: per-edge elementwise only — writes X rows (hi/lo f16) + rs
// ============================================================
__global__ void edge_kernel(const float* __restrict__ r_ij,
                            const int* __restrict__ dst,
                            const float* __restrict__ W_enc,
                            const float* __restrict__ b_enc,
                            int n_edges)
{
    __shared__ float sWencT[8 * 32];
    __shared__ float sbenc[32];
    int tid = threadIdx.x;
    if (tid < 256) { int cch = tid >> 3, k = tid & 7; sWencT[k * 32 + cch] = W_enc[tid]; }
    if (tid < 32) sbenc[tid] = b_enc[tid];
    __syncthreads();

    int w = tid >> 5, c = tid & 31;

#pragma unroll
    for (int ei = 0; ei < 4; ei++) {
        int e = blockIdx.x * 32 + ei * 8 + w;
        if (e >= n_edges) continue;

        float r0 = __ldg(r_ij + (size_t)e * 3 + 0);
        float r1 = __ldg(r_ij + (size_t)e * 3 + 1);
        float r2 = __ldg(r_ij + (size_t)e * 3 + 2);
        float rr = sqrtf(r0 * r0 + r1 * r1 + r2 * r2);

        float ex = 0.f;
        if (c < 8) {
            float ctr = (5.0f / 7.0f) * (float)c;
            float dd = (rr - ctr) * (8.0f / 5.0f);
            ex = expf(-dd * dd);
        }
        float renc = sbenc[c];
#pragma unroll
        for (int k = 0; k < 8; k++)
            renc += __shfl_sync(0xffffffffu, ex, k) * sWencT[k * 32 + c];

        float nn = 1.4f * rr;
        float th = tanhf(nn) / fmaxf(nn, 1e-6f);
        float rs0 = 1.4f * r0 * th, rs1 = 1.4f * r1 * th, rs2 = 1.4f * r2 * th;

        int dn = __ldg(dst + e);
        float la = __ldg(g_la + (size_t)dn * 32 + c);
        float t0 = renc * __ldg(g_lv + (size_t)dn * 96 + 0 + c);
        float t1 = renc * __ldg(g_lv + (size_t)dn * 96 + 32 + c);
        float t2 = renc * __ldg(g_lv + (size_t)dn * 96 + 64 + c);

        float y000 = la * renc;
        float y110 = t0 * rs0 + t1 * rs1 + t2 * rs2;
        float u0 = t1 * rs2 - t2 * rs1;
        float u1 = t2 * rs0 - t0 * rs2;
        float u2 = t0 * rs1 - t1 * rs0;

        if (c == 0) g_rs4[e] = make_float4(rs0, rs1, rs2, 0.f);

        float vals[8] = {y000, y110, t0, u0, t1, u1, t2, u2};
        size_t xb = (size_t)e * 256 + c;
#pragma unroll
        for (int j = 0; j < 8; j++) {
            float v = vals[j];
            __half h = __float2half_rn(v);
            __half l = __float2half_rn(v - __half2float(h));
            g_Xh[xb + j * 32] = h;
            g_Xl[xb + j * 32] = l;
        }
    }
}

// ============================================================
// Kernel 3: fused front-GEMMs + 3-layer MLP via mma.sync
// 128 threads, 2 CTAs/SM, 64-row tiles, single W buffer
// residual psi_a0 kept in registers (acc_a) across the whole tile
// ============================================================
#define ROWB 272
#define A_HI_OFF 0
#define A_LO_OFF 17408
#define W_HI_OFF 34816
#define W_LO_OFF 69632
#define SRS_OFF  104448
#define SRC_OFF  105472
#define SB_OFF   105728
#define MLP_DSMEM 106752

__device__ __forceinline__ void stage_W(uint32_t sbase, int l, int tid) {
    const uint4* shi = (const uint4*)g_Whl[l][0];
    const uint4* slo = (const uint4*)g_Whl[l][1];
#pragma unroll
    for (int it = 0; it < 16; it++) {
        int i = it * 128 + tid;              // 2048 uint4 per image
        int n = i >> 4, k8 = i & 15;
        uint32_t d = (uint32_t)n * ROWB + k8 * 16;
        CP_ASYNC16(sbase + W_HI_OFF + d, shi + i);
        CP_ASYNC16(sbase + W_LO_OFF + d, slo + i);
    }
}

__device__ __forceinline__ void stage_X(uint32_t sbase, int tile, int half, int tid) {
    const uint32_t* xh = (const uint32_t*)g_Xh + (size_t)tile * 64 * 128 + half * 64;
    const uint32_t* xl = (const uint32_t*)g_Xl + (size_t)tile * 64 * 128 + half * 64;
#pragma unroll
    for (int it = 0; it < 8; it++) {
        int i = it * 128 + tid;              // 1024 uint4 per half (64 rows x 16)
        int r = i >> 4, k16 = i & 15;
        uint32_t d = (uint32_t)r * ROWB + k16 * 16;
        CP_ASYNC16(sbase + A_HI_OFF + d, xh + (size_t)r * 128 + k16 * 4);
        CP_ASYNC16(sbase + A_LO_OFF + d, xl + (size_t)r * 128 + k16 * 4);
    }
}

template <int K0, int K1>
__device__ __forceinline__ void layer_mma(float acc[2][8][4], uint32_t aHi, uint32_t aLo,
                                          uint32_t wHi, uint32_t wLo, uint32_t bRow)
{
#pragma unroll
    for (int ks = K0; ks < K1; ks++) {
        uint32_t kb = (uint32_t)ks * 32;
        uint32_t ahi[2][4], alo[2][4], bhi[8][2], blo[8][2];
#pragma unroll
        for (int mf = 0; mf < 2; mf++) {
            ldsm_x4(ahi[mf], aHi + (uint32_t)mf * 16 * ROWB + kb);
            ldsm_x4(alo[mf], aLo + (uint32_t)mf * 16 * ROWB + kb);
        }
#pragma unroll
        for (int nf2 = 0; nf2 < 4; nf2++) {
            ldsm_x4(&bhi[2 * nf2][0], wHi + bRow + (uint32_t)nf2 * 16 * ROWB + kb);
            ldsm_x4(&blo[2 * nf2][0], wLo + bRow + (uint32_t)nf2 * 16 * ROWB + kb);
        }
#pragma unroll
        for (int mf = 0; mf < 2; mf++)
#pragma unroll
            for (int nf = 0; nf < 8; nf++) {
                mma16816(acc[mf][nf], ahi[mf], bhi[nf]);
                mma16816(acc[mf][nf], alo[mf], bhi[nf]);
                mma16816(acc[mf][nf], ahi[mf], blo[nf]);
            }
    }
}

// N=32 GEMM, 16-row A tile per warp
template <int K0, int K1>
__device__ __forceinline__ void small_mma(float acc[4][4], uint32_t aHi, uint32_t aLo,
                                          uint32_t wHi, uint32_t wLo, uint32_t bRowS)
{
#pragma unroll
    for (int ks = K0; ks < K1; ks++) {
        uint32_t akb = (uint32_t)ks * 32, bkb = (uint32_t)(ks - K0) * 32;
        uint32_t ah[4], al[4], bh[8], bl[8];
        ldsm_x4(ah, aHi + akb);
        ldsm_x4(al, aLo + akb);
#pragma unroll
        for (int nf2 = 0; nf2 < 2; nf2++) {
            ldsm_x4(&bh[4 * nf2], wHi + bRowS + (uint32_t)nf2 * 16 * ROWB + bkb);
            ldsm_x4(&bl[4 * nf2], wLo + bRowS + (uint32_t)nf2 * 16 * ROWB + bkb);
        }
#pragma unroll
        for (int nf = 0; nf < 4; nf++) {
            mma16816(acc[nf], ah, &bh[2 * nf]);
            mma16816(acc[nf], al, &bh[2 * nf]);
            mma16816(acc[nf], ah, &bl[2 * nf]);
        }
    }
}

__global__ void __launch_bounds__(128, 2)
mlp_kernel(const float* __restrict__ bm1,
           const float* __restrict__ bm2,
           const int* __restrict__ src,
           float* __restrict__ Ba,
           float* __restrict__ Bv,
           int n_edges, int ntiles)
{
    extern __shared__ __align__(16) char dsm[];

    uint32_t sbase = smem_u32(dsm);
    int tid = threadIdx.x;
    int lane = tid & 31, wid = tid >> 5;
    int wm = wid & 1, wn = wid >> 1;          // warp tile: rows wm*32, cols wn*64
    int q = lane & 3, rbase = lane >> 2;

    float* s_b = (float*)(dsm + SB_OFF);
    float4* srs = (float4*)(dsm + SRS_OFF);
    int* ssrc = (int*)(dsm + SRC_OFF);

    s_b[tid] = bm1[tid];
    s_b[128 + tid] = bm2[tid];

    uint32_t aRowHi = sbase + A_HI_OFF + (uint32_t)(wm * 32 + (lane & 15)) * ROWB + ((lane >> 4) << 4);
    uint32_t aRowLo = aRowHi + (A_LO_OFF - A_HI_OFF);
    uint32_t aRow16 = sbase + A_HI_OFF + (uint32_t)(wid * 16 + (lane & 15)) * ROWB + ((lane >> 4) << 4);
    uint32_t aRow16Lo = aRow16 + (A_LO_OFF - A_HI_OFF);
    uint32_t bRow  = (uint32_t)(wn * 64 + ((lane >> 4) << 3) + (lane & 7)) * ROWB + (((lane >> 3) & 1) << 4);
    uint32_t bRowP = (uint32_t)(64 + ((lane >> 4) << 3) + (lane & 7)) * ROWB + (((lane >> 3) & 1) << 4) + 128;
    uint32_t bRowV = (uint32_t)(96 + ((lane >> 4) << 3) + (lane & 7)) * ROWB + (((lane >> 3) & 1) << 4) + 128;

    uint32_t wHi = sbase + W_HI_OFF, wLo = sbase + W_LO_OFF;

    for (int tile = blockIdx.x; tile < ntiles; tile += gridDim.x) {
        // stage X half1 + front weights (W free: prev S4 synced at loop end)
        stage_X(sbase, tile, 0, tid);
        stage_W(sbase, 0, tid);
        CP_COMMIT();
        if (tid < 64) {
            int e = tile * 64 + tid;
            ssrc[tid] = (e < n_edges) ? src[e] : 0;
            srs[tid] = (e < n_edges) ? g_rs4[e] : make_float4(0.f, 0.f, 0.f, 0.f);
        }
        CP_WAIT0();
        __syncthreads();

        // ---- front set 1: psi_a0 (acc_a), p (acc_p), pv0 ----
        float acc_a[2][8][4];
#pragma unroll
        for (int mf = 0; mf < 2; mf++)
#pragma unroll
            for (int nf = 0; nf < 8; nf++)
#pragma unroll
                for (int t = 0; t < 4; t++) acc_a[mf][nf][t] = 0.f;
        layer_mma<0, 4>(acc_a, aRowHi, aRowLo, wHi, wLo, bRow);

        float acc_p[4][4], acc_v0[4][4];
#pragma unroll
        for (int nf = 0; nf < 4; nf++)
#pragma unroll
            for (int t = 0; t < 4; t++) { acc_p[nf][t] = 0.f; acc_v0[nf][t] = 0.f; }
        small_mma<0, 2>(acc_p, aRow16, aRow16Lo, wHi, wLo, bRowP);
        small_mma<4, 8>(acc_v0, aRow16, aRow16Lo, wHi, wLo, bRowV);
        __syncthreads();      // A reads done

        stage_X(sbase, tile, 1, tid); CP_COMMIT();

        // pv0 epilogue (comp 0)
#pragma unroll
        for (int nf = 0; nf < 4; nf++) {
            int col = nf * 8 + 2 * q;
#pragma unroll
            for (int h = 0; h < 2; h++) {
                int row = wid * 16 + rbase + h * 8;
                int e = tile * 64 + row;
                if (e >= n_edges) continue;
                float rsv = srs[row].x;
                int s = ssrc[row];
                float v0 = 0.1f * (acc_v0[nf][2 * h] + acc_p[nf][2 * h] * rsv);
                float v1 = 0.1f * (acc_v0[nf][2 * h + 1] + acc_p[nf][2 * h + 1] * rsv);
                red_f32(Bv + (size_t)s * 96 + col * 3, v0);
                red_f32(Bv + (size_t)s * 96 + (col + 1) * 3, v1);
            }
        }
        CP_WAIT0();
        __syncthreads();      // X half2 ready

        // ---- front set 2: pv1, pv2 ----
        float acc_v1[4][4], acc_v2[4][4];
#pragma unroll
        for (int nf = 0; nf < 4; nf++)
#pragma unroll
            for (int t = 0; t < 4; t++) { acc_v1[nf][t] = 0.f; acc_v2[nf][t] = 0.f; }
        small_mma<0, 4>(acc_v1, aRow16, aRow16Lo, wHi, wLo, bRowV);
        small_mma<4, 8>(acc_v2, aRow16, aRow16Lo, wHi, wLo, bRowV);
        __syncthreads();      // A + front-W reads done

        stage_W(sbase, 1, tid); CP_COMMIT();   // Wm1

        // write psi_a0 (acc_a) -> A hi/lo
#pragma unroll
        for (int mf = 0; mf < 2; mf++) {
            int row = wm * 32 + mf * 16 + rbase;
#pragma unroll
            for (int nf = 0; nf < 8; nf++) {
                int col = wn * 64 + nf * 8 + 2 * q;
#pragma unroll
                for (int h = 0; h < 2; h++) {
                    float x0 = acc_a[mf][nf][2 * h];
                    float x1 = acc_a[mf][nf][2 * h + 1];
                    __half hh0 = __float2half_rn(x0), hh1 = __float2half_rn(x1);
                    __half ll0 = __float2half_rn(x0 - __half2float(hh0));
                    __half ll1 = __float2half_rn(x1 - __half2float(hh1));
                    uint32_t off = (uint32_t)(row + h * 8) * ROWB + col * 2;
                    *(uint32_t*)(dsm + A_HI_OFF + off) = pack_h2(hh0, hh1);
                    *(uint32_t*)(dsm + A_LO_OFF + off) = pack_h2(ll0, ll1);
                }
            }
        }

        // pv1 / pv2 epilogues
#pragma unroll
        for (int comp = 1; comp < 3; comp++) {
            float (*av)[4] = (comp == 1) ? acc_v1 : acc_v2;
#pragma unroll
            for (int nf = 0; nf < 4; nf++) {
                int col = nf * 8 + 2 * q;
#pragma unroll
                for (int h = 0; h < 2; h++) {
                    int row = wid * 16 + rbase + h * 8;
                    int e = tile * 64 + row;
                    if (e >= n_edges) continue;
                    float rsv = (comp == 1) ? srs[row].y : srs[row].z;
                    int s = ssrc[row];
                    float v0 = 0.1f * (av[nf][2 * h] + acc_p[nf][2 * h] * rsv);
                    float v1 = 0.1f * (av[nf][2 * h + 1] + acc_p[nf][2 * h + 1] * rsv);
                    red_f32(Bv + (size_t)s * 96 + col * 3 + comp, v0);
                    red_f32(Bv + (size_t)s * 96 + (col + 1) * 3 + comp, v1);
                }
            }
        }
        CP_WAIT0();
        __syncthreads();      // Wm1 ready + A writes visible

        // ---- S2 / S3: hidden layers ----
        float acc[2][8][4];
#pragma unroll
        for (int l = 0; l < 2; l++) {
#pragma unroll
            for (int mf = 0; mf < 2; mf++)
#pragma unroll
                for (int nf = 0; nf < 8; nf++)
#pragma unroll
                    for (int t = 0; t < 4; t++) acc[mf][nf][t] = 0.f;
            layer_mma<0, 8>(acc, aRowHi, aRowLo, wHi, wLo, bRow);
            __syncthreads();  // W + A reads done

            stage_W(sbase, l + 2, tid); CP_COMMIT();  // next weights

#pragma unroll
            for (int mf = 0; mf < 2; mf++) {
                int row = wm * 32 + mf * 16 + rbase;
#pragma unroll
                for (int nf = 0; nf < 8; nf++) {
                    int col = wn * 64 + nf * 8 + 2 * q;
                    float b0 = s_b[l * 128 + col], b1 = s_b[l * 128 + col + 1];
#pragma unroll
                    for (int h = 0; h < 2; h++) {
                        float x0 = acc[mf][nf][2 * h] + b0;
                        float x1 = acc[mf][nf][2 * h + 1] + b1;
                        x0 = (x0 >= 0.f) ? x0 : 0.1f * x0;
                        x1 = (x1 >= 0.f) ? x1 : 0.1f * x1;
                        __half hh0 = __float2half_rn(x0), hh1 = __float2half_rn(x1);
                        __half ll0 = __float2half_rn(x0 - __half2float(hh0));
                        __half ll1 = __float2half_rn(x1 - __half2float(hh1));
                        uint32_t off = (uint32_t)(row + h * 8) * ROWB + col * 2;
                        *(uint32_t*)(dsm + A_HI_OFF + off) = pack_h2(hh0, hh1);
                        *(uint32_t*)(dsm + A_LO_OFF + off) = pack_h2(ll0, ll1);
                    }
                }
            }
            CP_WAIT0();
            __syncthreads();  // next W ready + A visible
        }

        // ---- S4 (Wm3) ----
#pragma unroll
        for (int mf = 0; mf < 2; mf++)
#pragma unroll
            for (int nf = 0; nf < 8; nf++)
#pragma unroll
                for (int t = 0; t < 4; t++) acc[mf][nf][t] = 0.f;
        layer_mma<0, 8>(acc, aRowHi, aRowLo, wHi, wLo, bRow);

        // residual (acc_a) + scale + scatter
#pragma unroll
        for (int mf = 0; mf < 2; mf++) {
            int row0 = wm * 32 + mf * 16 + rbase;
#pragma unroll
            for (int h = 0; h < 2; h++) {
                int row = row0 + h * 8;
                int e = tile * 64 + row;
                if (e >= n_edges) continue;
                int s = ssrc[row];
                float* bp = Ba + (size_t)s * 128;
#pragma unroll
                for (int nf = 0; nf < 8; nf++) {
                    int col = wn * 64 + nf * 8 + 2 * q;
                    red_v2(bp + col,
                           0.1f * (acc[mf][nf][2 * h] + acc_a[mf][nf][2 * h]),
                           0.1f * (acc[mf][nf][2 * h + 1] + acc_a[mf][nf][2 * h + 1]));
                }
            }
        }
        __syncthreads();      // protect A/W before next tile staging
    }
}

// ============================================================
extern "C" void kernel_launch(void* const* d_in, const int* in_sizes, int n_in,
                              void* d_out, int out_size)
{
    const float* x_a   = (const float*)d_in[0];
    const float* x_v   = (const float*)d_in[1];
    const float* r_ij  = (const float*)d_in[2];
    const int*   src   = (const int*)d_in[3];
    const int*   dst   = (const int*)d_in[4];
    const float* W_L0  = (const float*)d_in[5];
    const float* W_L1  = (const float*)d_in[6];
    const float* W_enc = (const float*)d_in[7];
    const float* b_enc = (const float*)d_in[8];
    const float* Wy000 = (const float*)d_in[9];
    const float* Wy110 = (const float*)d_in[10];
    const float* Wy011 = (const float*)d_in[11];
    const float* Wy101 = (const float*)d_in[12];
    const float* Wy111 = (const float*)d_in[13];
    const float* Wm1   = (const float*)d_in[14];
    const float* bm1   = (const float*)d_in[15];
    const float* Wm2   = (const float*)d_in[16];
    const float* bm2   = (const float*)d_in[17];
    const float* Wm3   = (const float*)d_in[18];

    int n_nodes = in_sizes[0] / 128;
    int n_edges = in_sizes[2] / 3;

    float* Ba = (float*)d_out;
    float* Bv = Ba + (size_t)n_nodes * 128;

    cudaMemsetAsync(d_out, 0, (size_t)out_size * sizeof(float), 0);

    wprep_kernel<<<4, 256>>>(Wm1, Wm2, Wm3, Wy000, Wy110, Wy011, Wy101, Wy111);

    node_proj_kernel<<<(n_nodes + 7) / 8, 256>>>(x_a, x_v, W_L0, W_L1, n_nodes);

    edge_kernel<<<(n_edges + 31) / 32, 256>>>(r_ij, dst, W_enc, b_enc, n_edges);

    cudaFuncSetAttribute(mlp_kernel, cudaFuncAttributeMaxDynamicSharedMemorySize, MLP_DSMEM);
    int ntiles = (n_edges + 63) / 64;
    int grid = ntiles < 296 ? ntiles : 296;
    mlp_kernel<<<grid, 128, MLP_DSMEM>>>(bm1, bm2, src, Ba, Bv, n_edges, ntiles);
}

// round 14
// speedup vs baseline: 4.0765x; 1.1633x over previous
#include <cuda_runtime.h>
#include <cuda_fp16.h>
#include <math.h>
#include <stdint.h>

#define MAX_NODES 50000
#define MAX_EDGES 500000
#define EPAD (MAX_EDGES + 128)

// ---- scratch (static device globals; no runtime allocation) ----
__device__ float g_la[MAX_NODES * 32];
__device__ float g_lv[MAX_NODES * 96];
__device__ __align__(16) __half g_Xh[(size_t)EPAD * 256];
__device__ __align__(16) __half g_Xl[(size_t)EPAD * 256];
__device__ float4 g_rs4[EPAD];
// weight images: [0]=combined front (Wc0|Wy011|WcV), [1..3]=Wm1..3; hi/lo
__device__ __align__(16) __half g_Whl[4][2][128 * 128];

// ============================================================
// helpers
// ============================================================
__device__ __forceinline__ uint32_t smem_u32(const void* p) {
    uint32_t a;
    asm("{ .reg .u64 t; cvta.to.shared.u64 t, %1; cvt.u32.u64 %0, t; }" : "=r"(a) : "l"(p));
    return a;
}
__device__ __forceinline__ void ldsm_x4(uint32_t r[4], uint32_t addr) {
    asm volatile("ldmatrix.sync.aligned.m8n8.x4.shared.b16 {%0,%1,%2,%3}, [%4];"
                 : "=r"(r[0]), "=r"(r[1]), "=r"(r[2]), "=r"(r[3]) : "r"(addr));
}
__device__ __forceinline__ void mma16816(float c[4], const uint32_t a[4], const uint32_t b[2]) {
    asm volatile("mma.sync.aligned.m16n8k16.row.col.f32.f16.f16.f32 "
                 "{%0,%1,%2,%3}, {%4,%5,%6,%7}, {%8,%9}, {%0,%1,%2,%3};"
                 : "+f"(c[0]), "+f"(c[1]), "+f"(c[2]), "+f"(c[3])
                 : "r"(a[0]), "r"(a[1]), "r"(a[2]), "r"(a[3]), "r"(b[0]), "r"(b[1]));
}
#define CP_ASYNC16(dst, src) \
    asm volatile("cp.async.cg.shared.global [%0], [%1], 16;" :: "r"(dst), "l"(src) : "memory")
#define CP_COMMIT() asm volatile("cp.async.commit_group;" ::: "memory")
#define CP_WAIT0()  asm volatile("cp.async.wait_group 0;" ::: "memory")

__device__ __forceinline__ void red_v2(float* p, float a, float b) {
    asm volatile("red.global.add.v2.f32 [%0], {%1,%2};" :: "l"(p), "f"(a), "f"(b) : "memory");
}
__device__ __forceinline__ void red_f32(float* p, float a) {
    asm volatile("red.global.add.f32 [%0], %1;" :: "l"(p), "f"(a) : "memory");
}
__device__ __forceinline__ uint32_t pack_h2(__half a, __half b) {
    __half2 t = __halves2half2(a, b);
    return *reinterpret_cast<uint32_t*>(&t);
}

// ============================================================
// Kernel 0: weight prep
// layer 0 image: k<64: [Wy000|Wy110]; rows 64..95,k 64..95: Wy011;
// rows 96..127, k 64..127: [Wy101|Wy111]; else 0.
// ============================================================
__global__ void wprep_kernel(const float* __restrict__ W1,
                             const float* __restrict__ W2,
                             const float* __restrict__ W3,
                             const float* __restrict__ Wy000,
                             const float* __restrict__ Wy110,
                             const float* __restrict__ Wy011,
                             const float* __restrict__ Wy101,
                             const float* __restrict__ Wy111)
{
    int L = blockIdx.x;
    for (int idx = threadIdx.x; idx < 128 * 128; idx += blockDim.x) {
        int n = idx >> 7, k = idx & 127;
        float wv = 0.f;
        if (L == 0) {
            if (k < 64) wv = (k < 32) ? Wy000[n * 32 + k] : Wy110[n * 32 + k - 32];
            else if (n >= 64 && n < 96 && k < 96) wv = Wy011[(n - 64) * 32 + (k - 64)];
            else if (n >= 96) wv = (k < 96) ? Wy101[(n - 96) * 32 + (k - 64)]
                                            : Wy111[(n - 96) * 32 + (k - 96)];
        } else {
            const float* Ws = (L == 1) ? W1 : (L == 2) ? W2 : W3;
            wv = Ws[idx];
        }
        __half hi = __float2half_rn(wv);
        __half lo = __float2half_rn(wv - __half2float(hi));
        g_Whl[L][0][idx] = hi;
        g_Whl[L][1][idx] = lo;
    }
}

// ============================================================
// Kernel 1: node projections
// ============================================================
__global__ void node_proj_kernel(const float* __restrict__ x_a,
                                 const float* __restrict__ x_v,
                                 const float* __restrict__ W_L0,
                                 const float* __restrict__ W_L1,
                                 int n_nodes)
{
    __shared__ float sWL0T[128 * 32];
    __shared__ float sWL1T[32 * 32];
    __shared__ float sxa[8][128];
    __shared__ float sxv[8][96];

    int tid = threadIdx.x;
    for (int idx = tid; idx < 4096; idx += 256) { int c = idx >> 7, d = idx & 127; sWL0T[d * 32 + c] = W_L0[idx]; }
    for (int idx = tid; idx < 1024; idx += 256) { int c = idx >> 5, d = idx & 31;  sWL1T[d * 32 + c] = W_L1[idx]; }
    __syncthreads();

    int w = tid >> 5, c = tid & 31;
    int node = blockIdx.x * 8 + w;
    if (node >= n_nodes) return;

    *(float4*)&sxa[w][c * 4] = *(const float4*)(x_a + (size_t)node * 128 + c * 4);
    if (c < 24) *(float4*)&sxv[w][c * 4] = *(const float4*)(x_v + (size_t)node * 96 + c * 4);
    __syncwarp();

    float la = 0.f;
#pragma unroll 8
    for (int d = 0; d < 128; d++) la += sxa[w][d] * sWL0T[d * 32 + c];

    float lv0 = 0.f, lv1 = 0.f, lv2 = 0.f;
#pragma unroll 8
    for (int d = 0; d < 32; d++) {
        float wl = sWL1T[d * 32 + c];
        lv0 += sxv[w][d * 3 + 0] * wl;
        lv1 += sxv[w][d * 3 + 1] * wl;
        lv2 += sxv[w][d * 3 + 2] * wl;
    }
    g_la[node * 32 + c] = la;
    g_lv[node * 96 + 0 + c]  = lv0;
    g_lv[node * 96 + 32 + c] = lv1;
    g_lv[node * 96 + 64 + c] = lv2;
}

// ============================================================
// Kernel 2: per-edge elementwise only — writes X rows (hi/lo f16) + rs
// ============================================================
__global__ void edge_kernel(const float* __restrict__ r_ij,
                            const int* __restrict__ dst,
                            const float* __restrict__ W_enc,
                            const float* __restrict__ b_enc,
                            int n_edges)
{
    __shared__ float sWencT[8 * 32];
    __shared__ float sbenc[32];
    int tid = threadIdx.x;
    if (tid < 256) { int cch = tid >> 3, k = tid & 7; sWencT[k * 32 + cch] = W_enc[tid]; }
    if (tid < 32) sbenc[tid] = b_enc[tid];
    __syncthreads();

    int w = tid >> 5, c = tid & 31;

#pragma unroll
    for (int ei = 0; ei < 4; ei++) {
        int e = blockIdx.x * 32 + ei * 8 + w;
        if (e >= n_edges) continue;

        float r0 = __ldg(r_ij + (size_t)e * 3 + 0);
        float r1 = __ldg(r_ij + (size_t)e * 3 + 1);
        float r2 = __ldg(r_ij + (size_t)e * 3 + 2);
        float rr = sqrtf(r0 * r0 + r1 * r1 + r2 * r2);

        float ex = 0.f;
        if (c < 8) {
            float ctr = (5.0f / 7.0f) * (float)c;
            float dd = (rr - ctr) * (8.0f / 5.0f);
            ex = expf(-dd * dd);
        }
        float renc = sbenc[c];
#pragma unroll
        for (int k = 0; k < 8; k++)
            renc += __shfl_sync(0xffffffffu, ex, k) * sWencT[k * 32 + c];

        float nn = 1.4f * rr;
        float th = tanhf(nn) / fmaxf(nn, 1e-6f);
        float rs0 = 1.4f * r0 * th, rs1 = 1.4f * r1 * th, rs2 = 1.4f * r2 * th;

        int dn = __ldg(dst + e);
        float la = __ldg(g_la + (size_t)dn * 32 + c);
        float t0 = renc * __ldg(g_lv + (size_t)dn * 96 + 0 + c);
        float t1 = renc * __ldg(g_lv + (size_t)dn * 96 + 32 + c);
        float t2 = renc * __ldg(g_lv + (size_t)dn * 96 + 64 + c);

        float y000 = la * renc;
        float y110 = t0 * rs0 + t1 * rs1 + t2 * rs2;
        float u0 = t1 * rs2 - t2 * rs1;
        float u1 = t2 * rs0 - t0 * rs2;
        float u2 = t0 * rs1 - t1 * rs0;

        if (c == 0) g_rs4[e] = make_float4(rs0, rs1, rs2, 0.f);

        float vals[8] = {y000, y110, t0, u0, t1, u1, t2, u2};
        size_t xb = (size_t)e * 256 + c;
#pragma unroll
        for (int j = 0; j < 8; j++) {
            float v = vals[j];
            __half h = __float2half_rn(v);
            __half l = __float2half_rn(v - __half2float(h));
            g_Xh[xb + j * 32] = h;
            g_Xl[xb + j * 32] = l;
        }
    }
}

// ============================================================
// Kernel 3: fused front-GEMMs + 3-layer MLP via mma.sync
// 128 threads, 2 CTAs/SM, 64-row tiles
// front: 3-pass hi/lo; hidden+output: 2-pass (Ahi+Alo)xWhi
// ============================================================
#define ROWB 272
#define A_HI_OFF 0
#define A_LO_OFF 17408
#define W_HI_OFF 34816
#define W_LO_OFF 69632
#define SRS_OFF  104448
#define SRC_OFF  105472
#define SB_OFF   105728
#define MLP_DSMEM 106752

// full hi+lo stage (front image only)
__device__ __forceinline__ void stage_W(uint32_t sbase, int l, int tid) {
    const uint4* shi = (const uint4*)g_Whl[l][0];
    const uint4* slo = (const uint4*)g_Whl[l][1];
#pragma unroll
    for (int it = 0; it < 16; it++) {
        int i = it * 128 + tid;
        int n = i >> 4, k8 = i & 15;
        uint32_t d = (uint32_t)n * ROWB + k8 * 16;
        CP_ASYNC16(sbase + W_HI_OFF + d, shi + i);
        CP_ASYNC16(sbase + W_LO_OFF + d, slo + i);
    }
}
// hi-only stage (hidden layers, 2-pass)
__device__ __forceinline__ void stage_W_hi(uint32_t sbase, int l, int tid) {
    const uint4* shi = (const uint4*)g_Whl[l][0];
#pragma unroll
    for (int it = 0; it < 16; it++) {
        int i = it * 128 + tid;
        int n = i >> 4, k8 = i & 15;
        uint32_t d = (uint32_t)n * ROWB + k8 * 16;
        CP_ASYNC16(sbase + W_HI_OFF + d, shi + i);
    }
}

__device__ __forceinline__ void stage_X(uint32_t sbase, int tile, int half, int tid) {
    const uint32_t* xh = (const uint32_t*)g_Xh + (size_t)tile * 64 * 128 + half * 64;
    const uint32_t* xl = (const uint32_t*)g_Xl + (size_t)tile * 64 * 128 + half * 64;
#pragma unroll
    for (int it = 0; it < 8; it++) {
        int i = it * 128 + tid;
        int r = i >> 4, k16 = i & 15;
        uint32_t d = (uint32_t)r * ROWB + k16 * 16;
        CP_ASYNC16(sbase + A_HI_OFF + d, xh + (size_t)r * 128 + k16 * 4);
        CP_ASYNC16(sbase + A_LO_OFF + d, xl + (size_t)r * 128 + k16 * 4);
    }
}

// 3-pass (front): Ahi*Bhi + Alo*Bhi + Ahi*Blo
template <int K0, int K1>
__device__ __forceinline__ void layer_mma(float acc[2][8][4], uint32_t aHi, uint32_t aLo,
                                          uint32_t wHi, uint32_t wLo, uint32_t bRow)
{
#pragma unroll
    for (int ks = K0; ks < K1; ks++) {
        uint32_t kb = (uint32_t)ks * 32;
        uint32_t ahi[2][4], alo[2][4], bhi[8][2], blo[8][2];
#pragma unroll
        for (int mf = 0; mf < 2; mf++) {
            ldsm_x4(ahi[mf], aHi + (uint32_t)mf * 16 * ROWB + kb);
            ldsm_x4(alo[mf], aLo + (uint32_t)mf * 16 * ROWB + kb);
        }
#pragma unroll
        for (int nf2 = 0; nf2 < 4; nf2++) {
            ldsm_x4(&bhi[2 * nf2][0], wHi + bRow + (uint32_t)nf2 * 16 * ROWB + kb);
            ldsm_x4(&blo[2 * nf2][0], wLo + bRow + (uint32_t)nf2 * 16 * ROWB + kb);
        }
#pragma unroll
        for (int mf = 0; mf < 2; mf++)
#pragma unroll
            for (int nf = 0; nf < 8; nf++) {
                mma16816(acc[mf][nf], ahi[mf], bhi[nf]);
                mma16816(acc[mf][nf], alo[mf], bhi[nf]);
                mma16816(acc[mf][nf], ahi[mf], blo[nf]);
            }
    }
}

// 2-pass (hidden/output): (Ahi + Alo) * Bhi
template <int K0, int K1>
__device__ __forceinline__ void layer_mma2(float acc[2][8][4], uint32_t aHi, uint32_t aLo,
                                           uint32_t wHi, uint32_t bRow)
{
#pragma unroll
    for (int ks = K0; ks < K1; ks++) {
        uint32_t kb = (uint32_t)ks * 32;
        uint32_t ahi[2][4], alo[2][4], bhi[8][2];
#pragma unroll
        for (int mf = 0; mf < 2; mf++) {
            ldsm_x4(ahi[mf], aHi + (uint32_t)mf * 16 * ROWB + kb);
            ldsm_x4(alo[mf], aLo + (uint32_t)mf * 16 * ROWB + kb);
        }
#pragma unroll
        for (int nf2 = 0; nf2 < 4; nf2++)
            ldsm_x4(&bhi[2 * nf2][0], wHi + bRow + (uint32_t)nf2 * 16 * ROWB + kb);
#pragma unroll
        for (int mf = 0; mf < 2; mf++)
#pragma unroll
            for (int nf = 0; nf < 8; nf++) {
                mma16816(acc[mf][nf], ahi[mf], bhi[nf]);
                mma16816(acc[mf][nf], alo[mf], bhi[nf]);
            }
    }
}

// N=32 GEMM, 16-row A tile per warp (front, 3-pass)
template <int K0, int K1>
__device__ __forceinline__ void small_mma(float acc[4][4], uint32_t aHi, uint32_t aLo,
                                          uint32_t wHi, uint32_t wLo, uint32_t bRowS)
{
#pragma unroll
    for (int ks = K0; ks < K1; ks++) {
        uint32_t akb = (uint32_t)ks * 32, bkb = (uint32_t)(ks - K0) * 32;
        uint32_t ah[4], al[4], bh[8], bl[8];
        ldsm_x4(ah, aHi + akb);
        ldsm_x4(al, aLo + akb);
#pragma unroll
        for (int nf2 = 0; nf2 < 2; nf2++) {
            ldsm_x4(&bh[4 * nf2], wHi + bRowS + (uint32_t)nf2 * 16 * ROWB + bkb);
            ldsm_x4(&bl[4 * nf2], wLo + bRowS + (uint32_t)nf2 * 16 * ROWB + bkb);
        }
#pragma unroll
        for (int nf = 0; nf < 4; nf++) {
            mma16816(acc[nf], ah, &bh[2 * nf]);
            mma16816(acc[nf], al, &bh[2 * nf]);
            mma16816(acc[nf], ah, &bl[2 * nf]);
        }
    }
}

__global__ void __launch_bounds__(128, 2)
mlp_kernel(const float* __restrict__ bm1,
           const float* __restrict__ bm2,
           const int* __restrict__ src,
           float* __restrict__ Ba,
           float* __restrict__ Bv,
           int n_edges, int ntiles)
{
    extern __shared__ __align__(16) char dsm[];

    uint32_t sbase = smem_u32(dsm);
    int tid = threadIdx.x;
    int lane = tid & 31, wid = tid >> 5;
    int wm = wid & 1, wn = wid >> 1;
    int q = lane & 3, rbase = lane >> 2;

    float* s_b = (float*)(dsm + SB_OFF);
    float4* srs = (float4*)(dsm + SRS_OFF);
    int* ssrc = (int*)(dsm + SRC_OFF);

    s_b[tid] = bm1[tid];
    s_b[128 + tid] = bm2[tid];

    uint32_t aRowHi = sbase + A_HI_OFF + (uint32_t)(wm * 32 + (lane & 15)) * ROWB + ((lane >> 4) << 4);
    uint32_t aRowLo = aRowHi + (A_LO_OFF - A_HI_OFF);
    uint32_t aRow16 = sbase + A_HI_OFF + (uint32_t)(wid * 16 + (lane & 15)) * ROWB + ((lane >> 4) << 4);
    uint32_t aRow16Lo = aRow16 + (A_LO_OFF - A_HI_OFF);
    uint32_t bRow  = (uint32_t)(wn * 64 + ((lane >> 4) << 3) + (lane & 7)) * ROWB + (((lane >> 3) & 1) << 4);
    uint32_t bRowP = (uint32_t)(64 + ((lane >> 4) << 3) + (lane & 7)) * ROWB + (((lane >> 3) & 1) << 4) + 128;
    uint32_t bRowV = (uint32_t)(96 + ((lane >> 4) << 3) + (lane & 7)) * ROWB + (((lane >> 3) & 1) << 4) + 128;

    uint32_t wHi = sbase + W_HI_OFF, wLo = sbase + W_LO_OFF;

    for (int tile = blockIdx.x; tile < ntiles; tile += gridDim.x) {
        stage_X(sbase, tile, 0, tid);
        stage_W(sbase, 0, tid);
        CP_COMMIT();
        if (tid < 64) {
            int e = tile * 64 + tid;
            ssrc[tid] = (e < n_edges) ? src[e] : 0;
            srs[tid] = (e < n_edges) ? g_rs4[e] : make_float4(0.f, 0.f, 0.f, 0.f);
        }
        CP_WAIT0();
        __syncthreads();

        // ---- front set 1: psi_a0 (acc_a), p (acc_p), pv0 ----
        float acc_a[2][8][4];
#pragma unroll
        for (int mf = 0; mf < 2; mf++)
#pragma unroll
            for (int nf = 0; nf < 8; nf++)
#pragma unroll
                for (int t = 0; t < 4; t++) acc_a[mf][nf][t] = 0.f;
        layer_mma<0, 4>(acc_a, aRowHi, aRowLo, wHi, wLo, bRow);

        float acc_p[4][4], acc_v0[4][4];
#pragma unroll
        for (int nf = 0; nf < 4; nf++)
#pragma unroll
            for (int t = 0; t < 4; t++) { acc_p[nf][t] = 0.f; acc_v0[nf][t] = 0.f; }
        small_mma<0, 2>(acc_p, aRow16, aRow16Lo, wHi, wLo, bRowP);
        small_mma<4, 8>(acc_v0, aRow16, aRow16Lo, wHi, wLo, bRowV);
        __syncthreads();

        stage_X(sbase, tile, 1, tid); CP_COMMIT();

        // pv0 epilogue
#pragma unroll
        for (int nf = 0; nf < 4; nf++) {
            int col = nf * 8 + 2 * q;
#pragma unroll
            for (int h = 0; h < 2; h++) {
                int row = wid * 16 + rbase + h * 8;
                int e = tile * 64 + row;
                if (e >= n_edges) continue;
                float rsv = srs[row].x;
                int s = ssrc[row];
                float v0 = 0.1f * (acc_v0[nf][2 * h] + acc_p[nf][2 * h] * rsv);
                float v1 = 0.1f * (acc_v0[nf][2 * h + 1] + acc_p[nf][2 * h + 1] * rsv);
                red_f32(Bv + (size_t)s * 96 + col * 3, v0);
                red_f32(Bv + (size_t)s * 96 + (col + 1) * 3, v1);
            }
        }
        CP_WAIT0();
        __syncthreads();

        // ---- front set 2: pv1, pv2 ----
        float acc_v1[4][4], acc_v2[4][4];
#pragma unroll
        for (int nf = 0; nf < 4; nf++)
#pragma unroll
            for (int t = 0; t < 4; t++) { acc_v1[nf][t] = 0.f; acc_v2[nf][t] = 0.f; }
        small_mma<0, 4>(acc_v1, aRow16, aRow16Lo, wHi, wLo, bRowV);
        small_mma<4, 8>(acc_v2, aRow16, aRow16Lo, wHi, wLo, bRowV);
        __syncthreads();

        stage_W_hi(sbase, 1, tid); CP_COMMIT();   // Wm1 (hi only)

        // write psi_a0 (acc_a) -> A hi/lo
#pragma unroll
        for (int mf = 0; mf < 2; mf++) {
            int row = wm * 32 + mf * 16 + rbase;
#pragma unroll
            for (int nf = 0; nf < 8; nf++) {
                int col = wn * 64 + nf * 8 + 2 * q;
#pragma unroll
                for (int h = 0; h < 2; h++) {
                    float x0 = acc_a[mf][nf][2 * h];
                    float x1 = acc_a[mf][nf][2 * h + 1];
                    __half hh0 = __float2half_rn(x0), hh1 = __float2half_rn(x1);
                    __half ll0 = __float2half_rn(x0 - __half2float(hh0));
                    __half ll1 = __float2half_rn(x1 - __half2float(hh1));
                    uint32_t off = (uint32_t)(row + h * 8) * ROWB + col * 2;
                    *(uint32_t*)(dsm + A_HI_OFF + off) = pack_h2(hh0, hh1);
                    *(uint32_t*)(dsm + A_LO_OFF + off) = pack_h2(ll0, ll1);
                }
            }
        }

        // pv1 / pv2 epilogues
#pragma unroll
        for (int comp = 1; comp < 3; comp++) {
            float (*av)[4] = (comp == 1) ? acc_v1 : acc_v2;
#pragma unroll
            for (int nf = 0; nf < 4; nf++) {
                int col = nf * 8 + 2 * q;
#pragma unroll
                for (int h = 0; h < 2; h++) {
                    int row = wid * 16 + rbase + h * 8;
                    int e = tile * 64 + row;
                    if (e >= n_edges) continue;
                    float rsv = (comp == 1) ? srs[row].y : srs[row].z;
                    int s = ssrc[row];
                    float v0 = 0.1f * (av[nf][2 * h] + acc_p[nf][2 * h] * rsv);
                    float v1 = 0.1f * (av[nf][2 * h + 1] + acc_p[nf][2 * h + 1] * rsv);
                    red_f32(Bv + (size_t)s * 96 + col * 3 + comp, v0);
                    red_f32(Bv + (size_t)s * 96 + (col + 1) * 3 + comp, v1);
                }
            }
        }
        CP_WAIT0();
        __syncthreads();

        // ---- S2 / S3: hidden layers (2-pass) ----
        float acc[2][8][4];
#pragma unroll
        for (int l = 0; l < 2; l++) {
#pragma unroll
            for (int mf = 0; mf < 2; mf++)
#pragma unroll
                for (int nf = 0; nf < 8; nf++)
#pragma unroll
                    for (int t = 0; t < 4; t++) acc[mf][nf][t] = 0.f;
            layer_mma2<0, 8>(acc, aRowHi, aRowLo, wHi, bRow);
            __syncthreads();

            stage_W_hi(sbase, l + 2, tid); CP_COMMIT();

#pragma unroll
            for (int mf = 0; mf < 2; mf++) {
                int row = wm * 32 + mf * 16 + rbase;
#pragma unroll
                for (int nf = 0; nf < 8; nf++) {
                    int col = wn * 64 + nf * 8 + 2 * q;
                    float b0 = s_b[l * 128 + col], b1 = s_b[l * 128 + col + 1];
#pragma unroll
                    for (int h = 0; h < 2; h++) {
                        float x0 = acc[mf][nf][2 * h] + b0;
                        float x1 = acc[mf][nf][2 * h + 1] + b1;
                        x0 = (x0 >= 0.f) ? x0 : 0.1f * x0;
                        x1 = (x1 >= 0.f) ? x1 : 0.1f * x1;
                        __half hh0 = __float2half_rn(x0), hh1 = __float2half_rn(x1);
                        __half ll0 = __float2half_rn(x0 - __half2float(hh0));
                        __half ll1 = __float2half_rn(x1 - __half2float(hh1));
                        uint32_t off = (uint32_t)(row + h * 8) * ROWB + col * 2;
                        *(uint32_t*)(dsm + A_HI_OFF + off) = pack_h2(hh0, hh1);
                        *(uint32_t*)(dsm + A_LO_OFF + off) = pack_h2(ll0, ll1);
                    }
                }
            }
            CP_WAIT0();
            __syncthreads();
        }

        // ---- S4 (Wm3, 2-pass) ----
#pragma unroll
        for (int mf = 0; mf < 2; mf++)
#pragma unroll
            for (int nf = 0; nf < 8; nf++)
#pragma unroll
                for (int t = 0; t < 4; t++) acc[mf][nf][t] = 0.f;
        layer_mma2<0, 8>(acc, aRowHi, aRowLo, wHi, bRow);

        // residual (acc_a) + scale + scatter
#pragma unroll
        for (int mf = 0; mf < 2; mf++) {
            int row0 = wm * 32 + mf * 16 + rbase;
#pragma unroll
            for (int h = 0; h < 2; h++) {
                int row = row0 + h * 8;
                int e = tile * 64 + row;
                if (e >= n_edges) continue;
                int s = ssrc[row];
                float* bp = Ba + (size_t)s * 128;
#pragma unroll
                for (int nf = 0; nf < 8; nf++) {
                    int col = wn * 64 + nf * 8 + 2 * q;
                    red_v2(bp + col,
                           0.1f * (acc[mf][nf][2 * h] + acc_a[mf][nf][2 * h]),
                           0.1f * (acc[mf][nf][2 * h + 1] + acc_a[mf][nf][2 * h + 1]));
                }
            }
        }
        __syncthreads();
    }
}

// ============================================================
extern "C" void kernel_launch(void* const* d_in, const int* in_sizes, int n_in,
                              void* d_out, int out_size)
{
    const float* x_a   = (const float*)d_in[0];
    const float* x_v   = (const float*)d_in[1];
    const float* r_ij  = (const float*)d_in[2];
    const int*   src   = (const int*)d_in[3];
    const int*   dst   = (const int*)d_in[4];
    const float* W_L0  = (const float*)d_in[5];
    const float* W_L1  = (const float*)d_in[6];
    const float* W_enc = (const float*)d_in[7];
    const float* b_enc = (const float*)d_in[8];
    const float* Wy000 = (const float*)d_in[9];
    const float* Wy110 = (const float*)d_in[10];
    const float* Wy011 = (const float*)d_in[11];
    const float* Wy101 = (const float*)d_in[12];
    const float* Wy111 = (const float*)d_in[13];
    const float* Wm1   = (const float*)d_in[14];
    const float* bm1   = (const float*)d_in[15];
    const float* Wm2   = (const float*)d_in[16];
    const float* bm2   = (const float*)d_in[17];
    const float* Wm3   = (const float*)d_in[18];

    int n_nodes = in_sizes[0] / 128;
    int n_edges = in_sizes[2] / 3;

    float* Ba = (float*)d_out;
    float* Bv = Ba + (size_t)n_nodes * 128;

    cudaMemsetAsync(d_out, 0, (size_t)out_size * sizeof(float), 0);

    wprep_kernel<<<4, 256>>>(Wm1, Wm2, Wm3, Wy000, Wy110, Wy011, Wy101, Wy111);

    node_proj_kernel<<<(n_nodes + 7) / 8, 256>>>(x_a, x_v, W_L0, W_L1, n_nodes);

    edge_kernel<<<(n_edges + 31) / 32, 256>>>(r_ij, dst, W_enc, b_enc, n_edges);

    cudaFuncSetAttribute(mlp_kernel, cudaFuncAttributeMaxDynamicSharedMemorySize, MLP_DSMEM);
    int ntiles = (n_edges + 63) / 64;
    int grid = ntiles < 296 ? ntiles : 296;
    mlp_kernel<<<grid, 128, MLP_DSMEM>>>(bm1, bm2, src, Ba, Bv, n_edges, ntiles);
}

// round 16
// speedup vs baseline: 6.5131x; 1.5977x over previous
#include <cuda_runtime.h>
#include <cuda_fp16.h>
#include <math.h>
#include <stdint.h>

#define MAX_NODES 50000
#define MAX_EDGES 500000
#define EPAD (MAX_EDGES + 128)

// ---- scratch (static device globals; no runtime allocation) ----
__device__ float g_la[MAX_NODES * 32];
__device__ float g_lv[MAX_NODES * 96];
__device__ __align__(16) __half g_Xh[(size_t)EPAD * 256];
__device__ __align__(16) __half g_Xl[(size_t)EPAD * 256];
__device__ float4 g_rs4[EPAD];
// weight images (f16 hi only): [0]=combined front (Wc0|Wy011|WcV), [1..3]=Wm1..3
__device__ __align__(16) __half g_Whl[4][128 * 128];

// ============================================================
// helpers
// ============================================================
__device__ __forceinline__ uint32_t smem_u32(const void* p) {
    uint32_t a;
    asm("{ .reg .u64 t; cvta.to.shared.u64 t, %1; cvt.u32.u64 %0, t; }" : "=r"(a) : "l"(p));
    return a;
}
__device__ __forceinline__ void ldsm_x4(uint32_t r[4], uint32_t addr) {
    asm volatile("ldmatrix.sync.aligned.m8n8.x4.shared.b16 {%0,%1,%2,%3}, [%4];"
                 : "=r"(r[0]), "=r"(r[1]), "=r"(r[2]), "=r"(r[3]) : "r"(addr));
}
__device__ __forceinline__ void mma16816(float c[4], const uint32_t a[4], const uint32_t b[2]) {
    asm volatile("mma.sync.aligned.m16n8k16.row.col.f32.f16.f16.f32 "
                 "{%0,%1,%2,%3}, {%4,%5,%6,%7}, {%8,%9}, {%0,%1,%2,%3};"
                 : "+f"(c[0]), "+f"(c[1]), "+f"(c[2]), "+f"(c[3])
                 : "r"(a[0]), "r"(a[1]), "r"(a[2]), "r"(a[3]), "r"(b[0]), "r"(b[1]));
}
#define CP_ASYNC16(dst, src) \
    asm volatile("cp.async.cg.shared.global [%0], [%1], 16;" :: "r"(dst), "l"(src) : "memory")
#define CP_COMMIT() asm volatile("cp.async.commit_group;" ::: "memory")
#define CP_WAIT0()  asm volatile("cp.async.wait_group 0;" ::: "memory")

__device__ __forceinline__ void red_v2(float* p, float a, float b) {
    asm volatile("red.global.add.v2.f32 [%0], {%1,%2};" :: "l"(p), "f"(a), "f"(b) : "memory");
}
__device__ __forceinline__ void red_f32(float* p, float a) {
    asm volatile("red.global.add.f32 [%0], %1;" :: "l"(p), "f"(a) : "memory");
}
__device__ __forceinline__ uint32_t pack_h2(__half a, __half b) {
    __half2 t = __halves2half2(a, b);
    return *reinterpret_cast<uint32_t*>(&t);
}

// ============================================================
// Kernel 0: weight prep (hi images only)
// layer 0 image: k<64: [Wy000|Wy110]; rows 64..95,k 64..95: Wy011;
// rows 96..127, k 64..127: [Wy101|Wy111]; else 0.
// ============================================================
__global__ void wprep_kernel(const float* __restrict__ W1,
                             const float* __restrict__ W2,
                             const float* __restrict__ W3,
                             const float* __restrict__ Wy000,
                             const float* __restrict__ Wy110,
                             const float* __restrict__ Wy011,
                             const float* __restrict__ Wy101,
                             const float* __restrict__ Wy111)
{
    int L = blockIdx.x;
    for (int idx = threadIdx.x; idx < 128 * 128; idx += blockDim.x) {
        int n = idx >> 7, k = idx & 127;
        float wv = 0.f;
        if (L == 0) {
            if (k < 64) wv = (k < 32) ? Wy000[n * 32 + k] : Wy110[n * 32 + k - 32];
            else if (n >= 64 && n < 96 && k < 96) wv = Wy011[(n - 64) * 32 + (k - 64)];
            else if (n >= 96) wv = (k < 96) ? Wy101[(n - 96) * 32 + (k - 64)]
                                            : Wy111[(n - 96) * 32 + (k - 96)];
        } else {
            const float* Ws = (L == 1) ? W1 : (L == 2) ? W2 : W3;
            wv = Ws[idx];
        }
        g_Whl[L][idx] = __float2half_rn(wv);
    }
}

// ============================================================
// Kernel 1: node projections
// ============================================================
__global__ void node_proj_kernel(const float* __restrict__ x_a,
                                 const float* __restrict__ x_v,
                                 const float* __restrict__ W_L0,
                                 const float* __restrict__ W_L1,
                                 int n_nodes)
{
    __shared__ float sWL0T[128 * 32];
    __shared__ float sWL1T[32 * 32];
    __shared__ float sxa[8][128];
    __shared__ float sxv[8][96];

    int tid = threadIdx.x;
    for (int idx = tid; idx < 4096; idx += 256) { int c = idx >> 7, d = idx & 127; sWL0T[d * 32 + c] = W_L0[idx]; }
    for (int idx = tid; idx < 1024; idx += 256) { int c = idx >> 5, d = idx & 31;  sWL1T[d * 32 + c] = W_L1[idx]; }
    __syncthreads();

    int w = tid >> 5, c = tid & 31;
    int node = blockIdx.x * 8 + w;
    if (node >= n_nodes) return;

    *(float4*)&sxa[w][c * 4] = *(const float4*)(x_a + (size_t)node * 128 + c * 4);
    if (c < 24) *(float4*)&sxv[w][c * 4] = *(const float4*)(x_v + (size_t)node * 96 + c * 4);
    __syncwarp();

    float la = 0.f;
#pragma unroll 8
    for (int d = 0; d < 128; d++) la += sxa[w][d] * sWL0T[d * 32 + c];

    float lv0 = 0.f, lv1 = 0.f, lv2 = 0.f;
#pragma unroll 8
    for (int d = 0; d < 32; d++) {
        float wl = sWL1T[d * 32 + c];
        lv0 += sxv[w][d * 3 + 0] * wl;
        lv1 += sxv[w][d * 3 + 1] * wl;
        lv2 += sxv[w][d * 3 + 2] * wl;
    }
    g_la[node * 32 + c] = la;
    g_lv[node * 96 + 0 + c]  = lv0;
    g_lv[node * 96 + 32 + c] = lv1;
    g_lv[node * 96 + 64 + c] = lv2;
}

// ============================================================
// Kernel 2: per-edge elementwise only — writes X rows (hi/lo f16) + rs
// ============================================================
__global__ void edge_kernel(const float* __restrict__ r_ij,
                            const int* __restrict__ dst,
                            const float* __restrict__ W_enc,
                            const float* __restrict__ b_enc,
                            int n_edges)
{
    __shared__ float sWencT[8 * 32];
    __shared__ float sbenc[32];
    int tid = threadIdx.x;
    if (tid < 256) { int cch = tid >> 3, k = tid & 7; sWencT[k * 32 + cch] = W_enc[tid]; }
    if (tid < 32) sbenc[tid] = b_enc[tid];
    __syncthreads();

    int w = tid >> 5, c = tid & 31;

#pragma unroll
    for (int ei = 0; ei < 4; ei++) {
        int e = blockIdx.x * 32 + ei * 8 + w;
        if (e >= n_edges) continue;

        float r0 = __ldg(r_ij + (size_t)e * 3 + 0);
        float r1 = __ldg(r_ij + (size_t)e * 3 + 1);
        float r2 = __ldg(r_ij + (size_t)e * 3 + 2);
        float rr = sqrtf(r0 * r0 + r1 * r1 + r2 * r2);

        float ex = 0.f;
        if (c < 8) {
            float ctr = (5.0f / 7.0f) * (float)c;
            float dd = (rr - ctr) * (8.0f / 5.0f);
            ex = expf(-dd * dd);
        }
        float renc = sbenc[c];
#pragma unroll
        for (int k = 0; k < 8; k++)
            renc += __shfl_sync(0xffffffffu, ex, k) * sWencT[k * 32 + c];

        float nn = 1.4f * rr;
        float th = tanhf(nn) / fmaxf(nn, 1e-6f);
        float rs0 = 1.4f * r0 * th, rs1 = 1.4f * r1 * th, rs2 = 1.4f * r2 * th;

        int dn = __ldg(dst + e);
        float la = __ldg(g_la + (size_t)dn * 32 + c);
        float t0 = renc * __ldg(g_lv + (size_t)dn * 96 + 0 + c);
        float t1 = renc * __ldg(g_lv + (size_t)dn * 96 + 32 + c);
        float t2 = renc * __ldg(g_lv + (size_t)dn * 96 + 64 + c);

        float y000 = la * renc;
        float y110 = t0 * rs0 + t1 * rs1 + t2 * rs2;
        float u0 = t1 * rs2 - t2 * rs1;
        float u1 = t2 * rs0 - t0 * rs2;
        float u2 = t0 * rs1 - t1 * rs0;

        if (c == 0) g_rs4[e] = make_float4(rs0, rs1, rs2, 0.f);

        float vals[8] = {y000, y110, t0, u0, t1, u1, t2, u2};
        size_t xb = (size_t)e * 256 + c;
#pragma unroll
        for (int j = 0; j < 8; j++) {
            float v = vals[j];
            __half h = __float2half_rn(v);
            __half l = __float2half_rn(v - __half2float(h));
            g_Xh[xb + j * 32] = h;
            g_Xl[xb + j * 32] = l;
        }
    }
}

// ============================================================
// Kernel 3: fused front-GEMMs + 3-layer MLP via mma.sync
// 256 threads, 1 CTA/SM, 128-row tiles
// ALL weight images resident in SMEM (staged once in prologue)
// all GEMMs 2-pass: (Ahi+Alo) x Whi
// ============================================================
#define ROWB 272
#define A_HI_OFF 0
#define A_LO_OFF 34816
#define W_OFF(l) (69632 + (l) * 34816)
#define SRS_OFF  208896
#define SRC_OFF  210944
#define SB_OFF   211456
#define MLP_DSMEM 212480

__device__ __forceinline__ void stage_W_hi(uint32_t sbase, int l, int tid) {
    const uint4* shi = (const uint4*)g_Whl[l];
#pragma unroll
    for (int it = 0; it < 8; it++) {
        int i = it * 256 + tid;              // 2048 uint4 per image
        int n = i >> 4, k8 = i & 15;
        uint32_t d = (uint32_t)n * ROWB + k8 * 16;
        CP_ASYNC16(sbase + W_OFF(l) + d, shi + i);
    }
}

// stage one 128-col half of X (hi+lo) for 128 rows
__device__ __forceinline__ void stage_X(uint32_t sbase, int tile, int half, int tid) {
    const uint32_t* xh = (const uint32_t*)g_Xh + (size_t)tile * 128 * 128 + half * 64;
    const uint32_t* xl = (const uint32_t*)g_Xl + (size_t)tile * 128 * 128 + half * 64;
#pragma unroll
    for (int it = 0; it < 8; it++) {
        int i = it * 256 + tid;              // 2048 uint4 per buffer
        int r = i >> 4, k16 = i & 15;
        uint32_t d = (uint32_t)r * ROWB + k16 * 16;
        CP_ASYNC16(sbase + A_HI_OFF + d, xh + (size_t)r * 128 + k16 * 4);
        CP_ASYNC16(sbase + A_LO_OFF + d, xl + (size_t)r * 128 + k16 * 4);
    }
}

// 2-pass: (Ahi + Alo) * Bhi
template <int K0, int K1>
__device__ __forceinline__ void layer_mma2(float acc[2][8][4], uint32_t aHi, uint32_t aLo,
                                           uint32_t wHi, uint32_t bRow)
{
#pragma unroll
    for (int ks = K0; ks < K1; ks++) {
        uint32_t kb = (uint32_t)ks * 32;
        uint32_t ahi[2][4], alo[2][4], bhi[8][2];
#pragma unroll
        for (int mf = 0; mf < 2; mf++) {
            ldsm_x4(ahi[mf], aHi + (uint32_t)mf * 16 * ROWB + kb);
            ldsm_x4(alo[mf], aLo + (uint32_t)mf * 16 * ROWB + kb);
        }
#pragma unroll
        for (int nf2 = 0; nf2 < 4; nf2++)
            ldsm_x4(&bhi[2 * nf2][0], wHi + bRow + (uint32_t)nf2 * 16 * ROWB + kb);
#pragma unroll
        for (int mf = 0; mf < 2; mf++)
#pragma unroll
            for (int nf = 0; nf < 8; nf++) {
                mma16816(acc[mf][nf], ahi[mf], bhi[nf]);
                mma16816(acc[mf][nf], alo[mf], bhi[nf]);
            }
    }
}

// N=32 GEMM, 16-row A tile per warp, 2-pass
template <int K0, int K1>
__device__ __forceinline__ void small_mma2(float acc[4][4], uint32_t aHi, uint32_t aLo,
                                           uint32_t wHi, uint32_t bRowS)
{
#pragma unroll
    for (int ks = K0; ks < K1; ks++) {
        uint32_t akb = (uint32_t)ks * 32, bkb = (uint32_t)(ks - K0) * 32;
        uint32_t ah[4], al[4], bh[8];
        ldsm_x4(ah, aHi + akb);
        ldsm_x4(al, aLo + akb);
#pragma unroll
        for (int nf2 = 0; nf2 < 2; nf2++)
            ldsm_x4(&bh[4 * nf2], wHi + bRowS + (uint32_t)nf2 * 16 * ROWB + bkb);
#pragma unroll
        for (int nf = 0; nf < 4; nf++) {
            mma16816(acc[nf], ah, &bh[2 * nf]);
            mma16816(acc[nf], al, &bh[2 * nf]);
        }
    }
}

__global__ void __launch_bounds__(256, 1)
mlp_kernel(const float* __restrict__ bm1,
           const float* __restrict__ bm2,
           const int* __restrict__ src,
           float* __restrict__ Ba,
           float* __restrict__ Bv,
           int n_edges, int ntiles)
{
    extern __shared__ __align__(16) char dsm[];

    uint32_t sbase = smem_u32(dsm);
    int tid = threadIdx.x;
    int lane = tid & 31, wid = tid >> 5;
    int wm = wid & 3, wn = wid >> 2;          // warp tile: rows wm*32, cols wn*64
    int q = lane & 3, rbase = lane >> 2;

    float* s_b = (float*)(dsm + SB_OFF);
    float4* srs = (float4*)(dsm + SRS_OFF);
    int* ssrc = (int*)(dsm + SRC_OFF);

    if (tid < 128) s_b[tid] = bm1[tid];
    else s_b[tid] = bm2[tid - 128];

    // ---- prologue: stage ALL weight images once ----
#pragma unroll
    for (int l = 0; l < 4; l++) stage_W_hi(sbase, l, tid);
    CP_COMMIT();
    CP_WAIT0();
    __syncthreads();

    uint32_t aRowHi = sbase + A_HI_OFF + (uint32_t)(wm * 32 + (lane & 15)) * ROWB + ((lane >> 4) << 4);
    uint32_t aRowLo = aRowHi + (A_LO_OFF - A_HI_OFF);
    uint32_t aRow16 = sbase + A_HI_OFF + (uint32_t)(wid * 16 + (lane & 15)) * ROWB + ((lane >> 4) << 4);
    uint32_t aRow16Lo = aRow16 + (A_LO_OFF - A_HI_OFF);
    uint32_t bRow  = (uint32_t)(wn * 64 + ((lane >> 4) << 3) + (lane & 7)) * ROWB + (((lane >> 3) & 1) << 4);
    uint32_t bRowP = (uint32_t)(64 + ((lane >> 4) << 3) + (lane & 7)) * ROWB + (((lane >> 3) & 1) << 4) + 128;
    uint32_t bRowV = (uint32_t)(96 + ((lane >> 4) << 3) + (lane & 7)) * ROWB + (((lane >> 3) & 1) << 4) + 128;

    uint32_t w0 = sbase + W_OFF(0), w1 = sbase + W_OFF(1);
    uint32_t w2 = sbase + W_OFF(2), w3 = sbase + W_OFF(3);

    for (int tile = blockIdx.x; tile < ntiles; tile += gridDim.x) {
        stage_X(sbase, tile, 0, tid);
        CP_COMMIT();
        if (tid < 128) {
            int e = tile * 128 + tid;
            ssrc[tid] = (e < n_edges) ? src[e] : 0;
            srs[tid] = (e < n_edges) ? g_rs4[e] : make_float4(0.f, 0.f, 0.f, 0.f);
        }
        CP_WAIT0();
        __syncthreads();

        // ---- front set 1: psi_a0 (acc_a), p (acc_p), pv0 ----
        float acc_a[2][8][4];
#pragma unroll
        for (int mf = 0; mf < 2; mf++)
#pragma unroll
            for (int nf = 0; nf < 8; nf++)
#pragma unroll
                for (int t = 0; t < 4; t++) acc_a[mf][nf][t] = 0.f;
        layer_mma2<0, 4>(acc_a, aRowHi, aRowLo, w0, bRow);

        float acc_p[4][4], acc_v0[4][4];
#pragma unroll
        for (int nf = 0; nf < 4; nf++)
#pragma unroll
            for (int t = 0; t < 4; t++) { acc_p[nf][t] = 0.f; acc_v0[nf][t] = 0.f; }
        small_mma2<0, 2>(acc_p, aRow16, aRow16Lo, w0, bRowP);
        small_mma2<4, 8>(acc_v0, aRow16, aRow16Lo, w0, bRowV);
        __syncthreads();      // A half0 reads done

        stage_X(sbase, tile, 1, tid); CP_COMMIT();

        // pv0 epilogue
#pragma unroll
        for (int nf = 0; nf < 4; nf++) {
            int col = nf * 8 + 2 * q;
#pragma unroll
            for (int h = 0; h < 2; h++) {
                int row = wid * 16 + rbase + h * 8;
                int e = tile * 128 + row;
                if (e >= n_edges) continue;
                float rsv = srs[row].x;
                int s = ssrc[row];
                float v0 = 0.1f * (acc_v0[nf][2 * h] + acc_p[nf][2 * h] * rsv);
                float v1 = 0.1f * (acc_v0[nf][2 * h + 1] + acc_p[nf][2 * h + 1] * rsv);
                red_f32(Bv + (size_t)s * 96 + col * 3, v0);
                red_f32(Bv + (size_t)s * 96 + (col + 1) * 3, v1);
            }
        }
        CP_WAIT0();
        __syncthreads();      // X half1 ready

        // ---- front set 2: pv1, pv2 ----
        float acc_v1[4][4], acc_v2[4][4];
#pragma unroll
        for (int nf = 0; nf < 4; nf++)
#pragma unroll
            for (int t = 0; t < 4; t++) { acc_v1[nf][t] = 0.f; acc_v2[nf][t] = 0.f; }
        small_mma2<0, 4>(acc_v1, aRow16, aRow16Lo, w0, bRowV);
        small_mma2<4, 8>(acc_v2, aRow16, aRow16Lo, w0, bRowV);
        __syncthreads();      // A reads done

        // write psi_a0 (acc_a) -> A hi/lo
#pragma unroll
        for (int mf = 0; mf < 2; mf++) {
            int row = wm * 32 + mf * 16 + rbase;
#pragma unroll
            for (int nf = 0; nf < 8; nf++) {
                int col = wn * 64 + nf * 8 + 2 * q;
#pragma unroll
                for (int h = 0; h < 2; h++) {
                    float x0 = acc_a[mf][nf][2 * h];
                    float x1 = acc_a[mf][nf][2 * h + 1];
                    __half hh0 = __float2half_rn(x0), hh1 = __float2half_rn(x1);
                    __half ll0 = __float2half_rn(x0 - __half2float(hh0));
                    __half ll1 = __float2half_rn(x1 - __half2float(hh1));
                    uint32_t off = (uint32_t)(row + h * 8) * ROWB + col * 2;
                    *(uint32_t*)(dsm + A_HI_OFF + off) = pack_h2(hh0, hh1);
                    *(uint32_t*)(dsm + A_LO_OFF + off) = pack_h2(ll0, ll1);
                }
            }
        }

        // pv1 / pv2 epilogues
#pragma unroll
        for (int comp = 1; comp < 3; comp++) {
            float (*av)[4] = (comp == 1) ? acc_v1 : acc_v2;
#pragma unroll
            for (int nf = 0; nf < 4; nf++) {
                int col = nf * 8 + 2 * q;
#pragma unroll
                for (int h = 0; h < 2; h++) {
                    int row = wid * 16 + rbase + h * 8;
                    int e = tile * 128 + row;
                    if (e >= n_edges) continue;
                    float rsv = (comp == 1) ? srs[row].y : srs[row].z;
                    int s = ssrc[row];
                    float v0 = 0.1f * (av[nf][2 * h] + acc_p[nf][2 * h] * rsv);
                    float v1 = 0.1f * (av[nf][2 * h + 1] + acc_p[nf][2 * h + 1] * rsv);
                    red_f32(Bv + (size_t)s * 96 + col * 3 + comp, v0);
                    red_f32(Bv + (size_t)s * 96 + (col + 1) * 3 + comp, v1);
                }
            }
        }
        __syncthreads();      // A (psi_a0) visible

        // ---- S2 / S3: hidden layers ----
        float acc[2][8][4];
#pragma unroll
        for (int l = 0; l < 2; l++) {
#pragma unroll
            for (int mf = 0; mf < 2; mf++)
#pragma unroll
                for (int nf = 0; nf < 8; nf++)
#pragma unroll
                    for (int t = 0; t < 4; t++) acc[mf][nf][t] = 0.f;
            layer_mma2<0, 8>(acc, aRowHi, aRowLo, (l == 0) ? w1 : w2, bRow);
            __syncthreads();  // A reads done

#pragma unroll
            for (int mf = 0; mf < 2; mf++) {
                int row = wm * 32 + mf * 16 + rbase;
#pragma unroll
                for (int nf = 0; nf < 8; nf++) {
                    int col = wn * 64 + nf * 8 + 2 * q;
                    float b0 = s_b[l * 128 + col], b1 = s_b[l * 128 + col + 1];
#pragma unroll
                    for (int h = 0; h < 2; h++) {
                        float x0 = acc[mf][nf][2 * h] + b0;
                        float x1 = acc[mf][nf][2 * h + 1] + b1;
                        x0 = (x0 >= 0.f) ? x0 : 0.1f * x0;
                        x1 = (x1 >= 0.f) ? x1 : 0.1f * x1;
                        __half hh0 = __float2half_rn(x0), hh1 = __float2half_rn(x1);
                        __half ll0 = __float2half_rn(x0 - __half2float(hh0));
                        __half ll1 = __float2half_rn(x1 - __half2float(hh1));
                        uint32_t off = (uint32_t)(row + h * 8) * ROWB + col * 2;
                        *(uint32_t*)(dsm + A_HI_OFF + off) = pack_h2(hh0, hh1);
                        *(uint32_t*)(dsm + A_LO_OFF + off) = pack_h2(ll0, ll1);
                    }
                }
            }
            __syncthreads();  // A writes visible
        }

        // ---- S4 (Wm3) ----
#pragma unroll
        for (int mf = 0; mf < 2; mf++)
#pragma unroll
            for (int nf = 0; nf < 8; nf++)
#pragma unroll
                for (int t = 0; t < 4; t++) acc[mf][nf][t] = 0.f;
        layer_mma2<0, 8>(acc, aRowHi, aRowLo, w3, bRow);

        // residual (acc_a) + scale + scatter
#pragma unroll
        for (int mf = 0; mf < 2; mf++) {
            int row0 = wm * 32 + mf * 16 + rbase;
#pragma unroll
            for (int h = 0; h < 2; h++) {
                int row = row0 + h * 8;
                int e = tile * 128 + row;
                if (e >= n_edges) continue;
                int s = ssrc[row];
                float* bp = Ba + (size_t)s * 128;
#pragma unroll
                for (int nf = 0; nf < 8; nf++) {
                    int col = wn * 64 + nf * 8 + 2 * q;
                    red_v2(bp + col,
                           0.1f * (acc[mf][nf][2 * h] + acc_a[mf][nf][2 * h]),
                           0.1f * (acc[mf][nf][2 * h + 1] + acc_a[mf][nf][2 * h + 1]));
                }
            }
        }
        __syncthreads();      // protect A before next tile's stage_X
    }
}

// ============================================================
extern "C" void kernel_launch(void* const* d_in, const int* in_sizes, int n_in,
                              void* d_out, int out_size)
{
    const float* x_a   = (const float*)d_in[0];
    const float* x_v   = (const float*)d_in[1];
    const float* r_ij  = (const float*)d_in[2];
    const int*   src   = (const int*)d_in[3];
    const int*   dst   = (const int*)d_in[4];
    const float* W_L0  = (const float*)d_in[5];
    const float* W_L1  = (const float*)d_in[6];
    const float* W_enc = (const float*)d_in[7];
    const float* b_enc = (const float*)d_in[8];
    const float* Wy000 = (const float*)d_in[9];
    const float* Wy110 = (const float*)d_in[10];
    const float* Wy011 = (const float*)d_in[11];
    const float* Wy101 = (const float*)d_in[12];
    const float* Wy111 = (const float*)d_in[13];
    const float* Wm1   = (const float*)d_in[14];
    const float* bm1   = (const float*)d_in[15];
    const float* Wm2   = (const float*)d_in[16];
    const float* bm2   = (const float*)d_in[17];
    const float* Wm3   = (const float*)d_in[18];

    int n_nodes = in_sizes[0] / 128;
    int n_edges = in_sizes[2] / 3;

    float* Ba = (float*)d_out;
    float* Bv = Ba + (size_t)n_nodes * 128;

    cudaMemsetAsync(d_out, 0, (size_t)out_size * sizeof(float), 0);

    wprep_kernel<<<4, 256>>>(Wm1, Wm2, Wm3, Wy000, Wy110, Wy011, Wy101, Wy111);

    node_proj_kernel<<<(n_nodes + 7) / 8, 256>>>(x_a, x_v, W_L0, W_L1, n_nodes);

    edge_kernel<<<(n_edges + 31) / 32, 256>>>(r_ij, dst, W_enc, b_enc, n_edges);

    cudaFuncSetAttribute(mlp_kernel, cudaFuncAttributeMaxDynamicSharedMemorySize, MLP_DSMEM);
    int ntiles = (n_edges + 127) / 128;
    int grid = ntiles < 148 ? ntiles : 148;
    mlp_kernel<<<grid, 256, MLP_DSMEM>>>(bm1, bm2, src, Ba, Bv, n_edges, ntiles);
}

// round 17
// speedup vs baseline: 6.5809x; 1.0104x over previous
#include <cuda_runtime.h>
#include <cuda_fp16.h>
#include <math.h>
#include <stdint.h>

#define MAX_NODES 50000
#define MAX_EDGES 500000
#define EPAD (MAX_EDGES + 128)

// ---- scratch (static device globals; no runtime allocation) ----
__device__ float g_la[MAX_NODES * 32];
__device__ float g_lv[MAX_NODES * 96];
__device__ __align__(16) __half g_Xh[(size_t)EPAD * 256];
__device__ __align__(16) __half g_Xl[(size_t)EPAD * 256];
__device__ float4 g_rs4[EPAD];
// weight images (f16 hi only): [0]=combined front (Wc0|Wy011|WcV), [1..3]=Wm1..3
__device__ __align__(16) __half g_Whl[4][128 * 128];

// ============================================================
// helpers
// ============================================================
__device__ __forceinline__ uint32_t smem_u32(const void* p) {
    uint32_t a;
    asm("{ .reg .u64 t; cvta.to.shared.u64 t, %1; cvt.u32.u64 %0, t; }" : "=r"(a) : "l"(p));
    return a;
}
__device__ __forceinline__ void ldsm_x4(uint32_t r[4], uint32_t addr) {
    asm volatile("ldmatrix.sync.aligned.m8n8.x4.shared.b16 {%0,%1,%2,%3}, [%4];"
                 : "=r"(r[0]), "=r"(r[1]), "=r"(r[2]), "=r"(r[3]) : "r"(addr));
}
__device__ __forceinline__ void mma16816(float c[4], const uint32_t a[4], const uint32_t b[2]) {
    asm volatile("mma.sync.aligned.m16n8k16.row.col.f32.f16.f16.f32 "
                 "{%0,%1,%2,%3}, {%4,%5,%6,%7}, {%8,%9}, {%0,%1,%2,%3};"
                 : "+f"(c[0]), "+f"(c[1]), "+f"(c[2]), "+f"(c[3])
                 : "r"(a[0]), "r"(a[1]), "r"(a[2]), "r"(a[3]), "r"(b[0]), "r"(b[1]));
}
#define CP_ASYNC16(dst, src) \
    asm volatile("cp.async.cg.shared.global [%0], [%1], 16;" :: "r"(dst), "l"(src) : "memory")
#define CP_COMMIT() asm volatile("cp.async.commit_group;" ::: "memory")
#define CP_WAIT0()  asm volatile("cp.async.wait_group 0;" ::: "memory")
// named barrier: 128 threads of one 4-warp group
#define BAR_G(id) asm volatile("bar.sync %0, 128;" :: "r"(id) : "memory")

__device__ __forceinline__ void red_v2(float* p, float a, float b) {
    asm volatile("red.global.add.v2.f32 [%0], {%1,%2};" :: "l"(p), "f"(a), "f"(b) : "memory");
}
__device__ __forceinline__ void red_f32(float* p, float a) {
    asm volatile("red.global.add.f32 [%0], %1;" :: "l"(p), "f"(a) : "memory");
}
__device__ __forceinline__ uint32_t pack_h2(__half a, __half b) {
    __half2 t = __halves2half2(a, b);
    return *reinterpret_cast<uint32_t*>(&t);
}

// ============================================================
// Kernel 0: weight prep (hi images only)
// ============================================================
__global__ void wprep_kernel(const float* __restrict__ W1,
                             const float* __restrict__ W2,
                             const float* __restrict__ W3,
                             const float* __restrict__ Wy000,
                             const float* __restrict__ Wy110,
                             const float* __restrict__ Wy011,
                             const float* __restrict__ Wy101,
                             const float* __restrict__ Wy111)
{
    int L = blockIdx.x;
    for (int idx = threadIdx.x; idx < 128 * 128; idx += blockDim.x) {
        int n = idx >> 7, k = idx & 127;
        float wv = 0.f;
        if (L == 0) {
            if (k < 64) wv = (k < 32) ? Wy000[n * 32 + k] : Wy110[n * 32 + k - 32];
            else if (n >= 64 && n < 96 && k < 96) wv = Wy011[(n - 64) * 32 + (k - 64)];
            else if (n >= 96) wv = (k < 96) ? Wy101[(n - 96) * 32 + (k - 64)]
                                            : Wy111[(n - 96) * 32 + (k - 96)];
        } else {
            const float* Ws = (L == 1) ? W1 : (L == 2) ? W2 : W3;
            wv = Ws[idx];
        }
        g_Whl[L][idx] = __float2half_rn(wv);
    }
}

// ============================================================
// Kernel 1: node projections
// ============================================================
__global__ void node_proj_kernel(const float* __restrict__ x_a,
                                 const float* __restrict__ x_v,
                                 const float* __restrict__ W_L0,
                                 const float* __restrict__ W_L1,
                                 int n_nodes)
{
    __shared__ float sWL0T[128 * 32];
    __shared__ float sWL1T[32 * 32];
    __shared__ float sxa[8][128];
    __shared__ float sxv[8][96];

    int tid = threadIdx.x;
    for (int idx = tid; idx < 4096; idx += 256) { int c = idx >> 7, d = idx & 127; sWL0T[d * 32 + c] = W_L0[idx]; }
    for (int idx = tid; idx < 1024; idx += 256) { int c = idx >> 5, d = idx & 31;  sWL1T[d * 32 + c] = W_L1[idx]; }
    __syncthreads();

    int w = tid >> 5, c = tid & 31;
    int node = blockIdx.x * 8 + w;
    if (node >= n_nodes) return;

    *(float4*)&sxa[w][c * 4] = *(const float4*)(x_a + (size_t)node * 128 + c * 4);
    if (c < 24) *(float4*)&sxv[w][c * 4] = *(const float4*)(x_v + (size_t)node * 96 + c * 4);
    __syncwarp();

    float la = 0.f;
#pragma unroll 8
    for (int d = 0; d < 128; d++) la += sxa[w][d] * sWL0T[d * 32 + c];

    float lv0 = 0.f, lv1 = 0.f, lv2 = 0.f;
#pragma unroll 8
    for (int d = 0; d < 32; d++) {
        float wl = sWL1T[d * 32 + c];
        lv0 += sxv[w][d * 3 + 0] * wl;
        lv1 += sxv[w][d * 3 + 1] * wl;
        lv2 += sxv[w][d * 3 + 2] * wl;
    }
    g_la[node * 32 + c] = la;
    g_lv[node * 96 + 0 + c]  = lv0;
    g_lv[node * 96 + 32 + c] = lv1;
    g_lv[node * 96 + 64 + c] = lv2;
}

// ============================================================
// Kernel 2: per-edge elementwise only — writes X rows (hi/lo f16) + rs
// ============================================================
__global__ void edge_kernel(const float* __restrict__ r_ij,
                            const int* __restrict__ dst,
                            const float* __restrict__ W_enc,
                            const float* __restrict__ b_enc,
                            int n_edges)
{
    __shared__ float sWencT[8 * 32];
    __shared__ float sbenc[32];
    int tid = threadIdx.x;
    if (tid < 256) { int cch = tid >> 3, k = tid & 7; sWencT[k * 32 + cch] = W_enc[tid]; }
    if (tid < 32) sbenc[tid] = b_enc[tid];
    __syncthreads();

    int w = tid >> 5, c = tid & 31;

#pragma unroll
    for (int ei = 0; ei < 4; ei++) {
        int e = blockIdx.x * 32 + ei * 8 + w;
        if (e >= n_edges) continue;

        float r0 = __ldg(r_ij + (size_t)e * 3 + 0);
        float r1 = __ldg(r_ij + (size_t)e * 3 + 1);
        float r2 = __ldg(r_ij + (size_t)e * 3 + 2);
        float rr = sqrtf(r0 * r0 + r1 * r1 + r2 * r2);

        float ex = 0.f;
        if (c < 8) {
            float ctr = (5.0f / 7.0f) * (float)c;
            float dd = (rr - ctr) * (8.0f / 5.0f);
            ex = expf(-dd * dd);
        }
        float renc = sbenc[c];
#pragma unroll
        for (int k = 0; k < 8; k++)
            renc += __shfl_sync(0xffffffffu, ex, k) * sWencT[k * 32 + c];

        float nn = 1.4f * rr;
        float th = tanhf(nn) / fmaxf(nn, 1e-6f);
        float rs0 = 1.4f * r0 * th, rs1 = 1.4f * r1 * th, rs2 = 1.4f * r2 * th;

        int dn = __ldg(dst + e);
        float la = __ldg(g_la + (size_t)dn * 32 + c);
        float t0 = renc * __ldg(g_lv + (size_t)dn * 96 + 0 + c);
        float t1 = renc * __ldg(g_lv + (size_t)dn * 96 + 32 + c);
        float t2 = renc * __ldg(g_lv + (size_t)dn * 96 + 64 + c);

        float y000 = la * renc;
        float y110 = t0 * rs0 + t1 * rs1 + t2 * rs2;
        float u0 = t1 * rs2 - t2 * rs1;
        float u1 = t2 * rs0 - t0 * rs2;
        float u2 = t0 * rs1 - t1 * rs0;

        if (c == 0) g_rs4[e] = make_float4(rs0, rs1, rs2, 0.f);

        float vals[8] = {y000, y110, t0, u0, t1, u1, t2, u2};
        size_t xb = (size_t)e * 256 + c;
#pragma unroll
        for (int j = 0; j < 8; j++) {
            float v = vals[j];
            __half h = __float2half_rn(v);
            __half l = __float2half_rn(v - __half2float(h));
            g_Xh[xb + j * 32] = h;
            g_Xl[xb + j * 32] = l;
        }
    }
}

// ============================================================
// Kernel 3: fused front-GEMMs + 3-layer MLP via mma.sync
// 256 threads = TWO independent 4-warp groups, each a 64-row pipeline
// with its own named barrier; weights SMEM-resident (staged once).
// all GEMMs 2-pass: (Ahi+Alo) x Whi
// ============================================================
#define ROWB 272
#define ATILE 17408                    // 64 rows * 272B
#define A_HI_G(g) ((uint32_t)(g) * ATILE)
#define A_LO_G(g) (34816u + (uint32_t)(g) * ATILE)
#define W_OFF(l) (69632 + (l) * 34816)
#define SRS_OFF  208896                // 2 groups * 64 * float4
#define SRC_OFF  210944                // 2 groups * 64 * int
#define SB_OFF   211456
#define MLP_DSMEM 212480

__device__ __forceinline__ void stage_W_hi(uint32_t sbase, int l, int tid) {
    const uint4* shi = (const uint4*)g_Whl[l];
#pragma unroll
    for (int it = 0; it < 8; it++) {
        int i = it * 256 + tid;
        int n = i >> 4, k8 = i & 15;
        uint32_t d = (uint32_t)n * ROWB + k8 * 16;
        CP_ASYNC16(sbase + W_OFF(l) + d, shi + i);
    }
}

// stage one 128-col half of X (hi+lo) for a 64-row group tile
__device__ __forceinline__ void stage_X_g(uint32_t sbase, uint32_t ahioff, uint32_t aloff,
                                          int tile, int half, int gtid) {
    const uint32_t* xh = (const uint32_t*)g_Xh + (size_t)tile * 64 * 128 + half * 64;
    const uint32_t* xl = (const uint32_t*)g_Xl + (size_t)tile * 64 * 128 + half * 64;
#pragma unroll
    for (int it = 0; it < 8; it++) {
        int i = it * 128 + gtid;             // 1024 uint4 per buffer
        int r = i >> 4, k16 = i & 15;
        uint32_t d = (uint32_t)r * ROWB + k16 * 16;
        CP_ASYNC16(sbase + ahioff + d, xh + (size_t)r * 128 + k16 * 4);
        CP_ASYNC16(sbase + aloff + d, xl + (size_t)r * 128 + k16 * 4);
    }
}

// 2-pass: (Ahi + Alo) * Bhi
template <int K0, int K1>
__device__ __forceinline__ void layer_mma2(float acc[2][8][4], uint32_t aHi, uint32_t aLo,
                                           uint32_t wHi, uint32_t bRow)
{
#pragma unroll
    for (int ks = K0; ks < K1; ks++) {
        uint32_t kb = (uint32_t)ks * 32;
        uint32_t ahi[2][4], alo[2][4], bhi[8][2];
#pragma unroll
        for (int mf = 0; mf < 2; mf++) {
            ldsm_x4(ahi[mf], aHi + (uint32_t)mf * 16 * ROWB + kb);
            ldsm_x4(alo[mf], aLo + (uint32_t)mf * 16 * ROWB + kb);
        }
#pragma unroll
        for (int nf2 = 0; nf2 < 4; nf2++)
            ldsm_x4(&bhi[2 * nf2][0], wHi + bRow + (uint32_t)nf2 * 16 * ROWB + kb);
#pragma unroll
        for (int mf = 0; mf < 2; mf++)
#pragma unroll
            for (int nf = 0; nf < 8; nf++) {
                mma16816(acc[mf][nf], ahi[mf], bhi[nf]);
                mma16816(acc[mf][nf], alo[mf], bhi[nf]);
            }
    }
}

// N=32 GEMM, 16-row A tile per warp, 2-pass
template <int K0, int K1>
__device__ __forceinline__ void small_mma2(float acc[4][4], uint32_t aHi, uint32_t aLo,
                                           uint32_t wHi, uint32_t bRowS)
{
#pragma unroll
    for (int ks = K0; ks < K1; ks++) {
        uint32_t akb = (uint32_t)ks * 32, bkb = (uint32_t)(ks - K0) * 32;
        uint32_t ah[4], al[4], bh[8];
        ldsm_x4(ah, aHi + akb);
        ldsm_x4(al, aLo + akb);
#pragma unroll
        for (int nf2 = 0; nf2 < 2; nf2++)
            ldsm_x4(&bh[4 * nf2], wHi + bRowS + (uint32_t)nf2 * 16 * ROWB + bkb);
#pragma unroll
        for (int nf = 0; nf < 4; nf++) {
            mma16816(acc[nf], ah, &bh[2 * nf]);
            mma16816(acc[nf], al, &bh[2 * nf]);
        }
    }
}

__global__ void __launch_bounds__(256, 1)
mlp_kernel(const float* __restrict__ bm1,
           const float* __restrict__ bm2,
           const int* __restrict__ src,
           float* __restrict__ Ba,
           float* __restrict__ Bv,
           int n_edges, int ntiles)
{
    extern __shared__ __align__(16) char dsm[];

    uint32_t sbase = smem_u32(dsm);
    int tid = threadIdx.x;
    int lane = tid & 31, wid = tid >> 5;
    int g = wid >> 2;                         // group 0/1
    int gtid = tid & 127;                     // thread within group
    int wg = wid & 3;                         // warp within group
    int wm = wg & 1, wn = wg >> 1;            // warp tile: rows wm*32, cols wn*64
    int q = lane & 3, rbase = lane >> 2;
    int barid = 1 + g;

    float* s_b = (float*)(dsm + SB_OFF);
    float4* srs = (float4*)(dsm + SRS_OFF) + g * 64;
    int* ssrc = (int*)(dsm + SRC_OFF) + g * 64;

    if (tid < 128) s_b[tid] = bm1[tid];
    else s_b[tid] = bm2[tid - 128];

    // ---- prologue: stage ALL weight images once (whole CTA) ----
#pragma unroll
    for (int l = 0; l < 4; l++) stage_W_hi(sbase, l, tid);
    CP_COMMIT();
    CP_WAIT0();
    __syncthreads();

    uint32_t ahioff = A_HI_G(g), aloff = A_LO_G(g);
    uint32_t aRowHi = sbase + ahioff + (uint32_t)(wm * 32 + (lane & 15)) * ROWB + ((lane >> 4) << 4);
    uint32_t aRowLo = aRowHi + (aloff - ahioff);
    uint32_t aRow16 = sbase + ahioff + (uint32_t)(wg * 16 + (lane & 15)) * ROWB + ((lane >> 4) << 4);
    uint32_t aRow16Lo = aRow16 + (aloff - ahioff);
    uint32_t bRow  = (uint32_t)(wn * 64 + ((lane >> 4) << 3) + (lane & 7)) * ROWB + (((lane >> 3) & 1) << 4);
    uint32_t bRowP = (uint32_t)(64 + ((lane >> 4) << 3) + (lane & 7)) * ROWB + (((lane >> 3) & 1) << 4) + 128;
    uint32_t bRowV = (uint32_t)(96 + ((lane >> 4) << 3) + (lane & 7)) * ROWB + (((lane >> 3) & 1) << 4) + 128;

    uint32_t w0 = sbase + W_OFF(0), w1 = sbase + W_OFF(1);
    uint32_t w2 = sbase + W_OFF(2), w3 = sbase + W_OFF(3);

    for (int tile = blockIdx.x * 2 + g; tile < ntiles; tile += gridDim.x * 2) {
        stage_X_g(sbase, ahioff, aloff, tile, 0, gtid);
        CP_COMMIT();
        if (gtid < 64) {
            int e = tile * 64 + gtid;
            ssrc[gtid] = (e < n_edges) ? src[e] : 0;
            srs[gtid] = (e < n_edges) ? g_rs4[e] : make_float4(0.f, 0.f, 0.f, 0.f);
        }
        CP_WAIT0();
        BAR_G(barid);

        // ---- front set 1: psi_a0 (acc_a), p (acc_p), pv0 ----
        float acc_a[2][8][4];
#pragma unroll
        for (int mf = 0; mf < 2; mf++)
#pragma unroll
            for (int nf = 0; nf < 8; nf++)
#pragma unroll
                for (int t = 0; t < 4; t++) acc_a[mf][nf][t] = 0.f;
        layer_mma2<0, 4>(acc_a, aRowHi, aRowLo, w0, bRow);

        float acc_p[4][4], acc_v0[4][4];
#pragma unroll
        for (int nf = 0; nf < 4; nf++)
#pragma unroll
            for (int t = 0; t < 4; t++) { acc_p[nf][t] = 0.f; acc_v0[nf][t] = 0.f; }
        small_mma2<0, 2>(acc_p, aRow16, aRow16Lo, w0, bRowP);
        small_mma2<4, 8>(acc_v0, aRow16, aRow16Lo, w0, bRowV);
        BAR_G(barid);         // A half0 reads done

        stage_X_g(sbase, ahioff, aloff, tile, 1, gtid); CP_COMMIT();

        // pv0 epilogue
#pragma unroll
        for (int nf = 0; nf < 4; nf++) {
            int col = nf * 8 + 2 * q;
#pragma unroll
            for (int h = 0; h < 2; h++) {
                int row = wg * 16 + rbase + h * 8;
                int e = tile * 64 + row;
                if (e >= n_edges) continue;
                float rsv = srs[row].x;
                int s = ssrc[row];
                float v0 = 0.1f * (acc_v0[nf][2 * h] + acc_p[nf][2 * h] * rsv);
                float v1 = 0.1f * (acc_v0[nf][2 * h + 1] + acc_p[nf][2 * h + 1] * rsv);
                red_f32(Bv + (size_t)s * 96 + col * 3, v0);
                red_f32(Bv + (size_t)s * 96 + (col + 1) * 3, v1);
            }
        }
        CP_WAIT0();
        BAR_G(barid);         // X half1 ready

        // ---- front set 2: pv1, pv2 ----
        float acc_v1[4][4], acc_v2[4][4];
#pragma unroll
        for (int nf = 0; nf < 4; nf++)
#pragma unroll
            for (int t = 0; t < 4; t++) { acc_v1[nf][t] = 0.f; acc_v2[nf][t] = 0.f; }
        small_mma2<0, 4>(acc_v1, aRow16, aRow16Lo, w0, bRowV);
        small_mma2<4, 8>(acc_v2, aRow16, aRow16Lo, w0, bRowV);
        BAR_G(barid);         // A reads done

        // write psi_a0 (acc_a) -> A hi/lo
#pragma unroll
        for (int mf = 0; mf < 2; mf++) {
            int row = wm * 32 + mf * 16 + rbase;
#pragma unroll
            for (int nf = 0; nf < 8; nf++) {
                int col = wn * 64 + nf * 8 + 2 * q;
#pragma unroll
                for (int h = 0; h < 2; h++) {
                    float x0 = acc_a[mf][nf][2 * h];
                    float x1 = acc_a[mf][nf][2 * h + 1];
                    __half hh0 = __float2half_rn(x0), hh1 = __float2half_rn(x1);
                    __half ll0 = __float2half_rn(x0 - __half2float(hh0));
                    __half ll1 = __float2half_rn(x1 - __half2float(hh1));
                    uint32_t off = (uint32_t)(row + h * 8) * ROWB + col * 2;
                    *(uint32_t*)(dsm + ahioff + off) = pack_h2(hh0, hh1);
                    *(uint32_t*)(dsm + aloff + off) = pack_h2(ll0, ll1);
                }
            }
        }

        // pv1 / pv2 epilogues
#pragma unroll
        for (int comp = 1; comp < 3; comp++) {
            float (*av)[4] = (comp == 1) ? acc_v1 : acc_v2;
#pragma unroll
            for (int nf = 0; nf < 4; nf++) {
                int col = nf * 8 + 2 * q;
#pragma unroll
                for (int h = 0; h < 2; h++) {
                    int row = wg * 16 + rbase + h * 8;
                    int e = tile * 64 + row;
                    if (e >= n_edges) continue;
                    float rsv = (comp == 1) ? srs[row].y : srs[row].z;
                    int s = ssrc[row];
                    float v0 = 0.1f * (av[nf][2 * h] + acc_p[nf][2 * h] * rsv);
                    float v1 = 0.1f * (av[nf][2 * h + 1] + acc_p[nf][2 * h + 1] * rsv);
                    red_f32(Bv + (size_t)s * 96 + col * 3 + comp, v0);
                    red_f32(Bv + (size_t)s * 96 + (col + 1) * 3 + comp, v1);
                }
            }
        }
        BAR_G(barid);         // A (psi_a0) visible

        // ---- S2 / S3: hidden layers ----
        float acc[2][8][4];
#pragma unroll
        for (int l = 0; l < 2; l++) {
#pragma unroll
            for (int mf = 0; mf < 2; mf++)
#pragma unroll
                for (int nf = 0; nf < 8; nf++)
#pragma unroll
                    for (int t = 0; t < 4; t++) acc[mf][nf][t] = 0.f;
            layer_mma2<0, 8>(acc, aRowHi, aRowLo, (l == 0) ? w1 : w2, bRow);
            BAR_G(barid);     // A reads done

#pragma unroll
            for (int mf = 0; mf < 2; mf++) {
                int row = wm * 32 + mf * 16 + rbase;
#pragma unroll
                for (int nf = 0; nf < 8; nf++) {
                    int col = wn * 64 + nf * 8 + 2 * q;
                    float b0 = s_b[l * 128 + col], b1 = s_b[l * 128 + col + 1];
#pragma unroll
                    for (int h = 0; h < 2; h++) {
                        float x0 = acc[mf][nf][2 * h] + b0;
                        float x1 = acc[mf][nf][2 * h + 1] + b1;
                        x0 = (x0 >= 0.f) ? x0 : 0.1f * x0;
                        x1 = (x1 >= 0.f) ? x1 : 0.1f * x1;
                        __half hh0 = __float2half_rn(x0), hh1 = __float2half_rn(x1);
                        __half ll0 = __float2half_rn(x0 - __half2float(hh0));
                        __half ll1 = __float2half_rn(x1 - __half2float(hh1));
                        uint32_t off = (uint32_t)(row + h * 8) * ROWB + col * 2;
                        *(uint32_t*)(dsm + ahioff + off) = pack_h2(hh0, hh1);
                        *(uint32_t*)(dsm + aloff + off) = pack_h2(ll0, ll1);
                    }
                }
            }
            BAR_G(barid);     // A writes visible
        }

        // ---- S4 (Wm3) ----
#pragma unroll
        for (int mf = 0; mf < 2; mf++)
#pragma unroll
            for (int nf = 0; nf < 8; nf++)
#pragma unroll
                for (int t = 0; t < 4; t++) acc[mf][nf][t] = 0.f;
        layer_mma2<0, 8>(acc, aRowHi, aRowLo, w3, bRow);

        // residual (acc_a) + scale + scatter
#pragma unroll
        for (int mf = 0; mf < 2; mf++) {
            int row0 = wm * 32 + mf * 16 + rbase;
#pragma unroll
            for (int h = 0; h < 2; h++) {
                int row = row0 + h * 8;
                int e = tile * 64 + row;
                if (e >= n_edges) continue;
                int s = ssrc[row];
                float* bp = Ba + (size_t)s * 128;
#pragma unroll
                for (int nf = 0; nf < 8; nf++) {
                    int col = wn * 64 + nf * 8 + 2 * q;
                    red_v2(bp + col,
                           0.1f * (acc[mf][nf][2 * h] + acc_a[mf][nf][2 * h]),
                           0.1f * (acc[mf][nf][2 * h + 1] + acc_a[mf][nf][2 * h + 1]));
                }
            }
        }
        BAR_G(barid);         // protect A before next tile's stage_X
    }
}

// ============================================================
extern "C" void kernel_launch(void* const* d_in, const int* in_sizes, int n_in,
                              void* d_out, int out_size)
{
    const float* x_a   = (const float*)d_in[0];
    const float* x_v   = (const float*)d_in[1];
    const float* r_ij  = (const float*)d_in[2];
    const int*   src   = (const int*)d_in[3];
    const int*   dst   = (const int*)d_in[4];
    const float* W_L0  = (const float*)d_in[5];
    const float* W_L1  = (const float*)d_in[6];
    const float* W_enc = (const float*)d_in[7];
    const float* b_enc = (const float*)d_in[8];
    const float* Wy000 = (const float*)d_in[9];
    const float* Wy110 = (const float*)d_in[10];
    const float* Wy011 = (const float*)d_in[11];
    const float* Wy101 = (const float*)d_in[12];
    const float* Wy111 = (const float*)d_in[13];
    const float* Wm1   = (const float*)d_in[14];
    const float* bm1   = (const float*)d_in[15];
    const float* Wm2   = (const float*)d_in[16];
    const float* bm2   = (const float*)d_in[17];
    const float* Wm3   = (const float*)d_in[18];

    int n_nodes = in_sizes[0] / 128;
    int n_edges = in_sizes[2] / 3;

    float* Ba = (float*)d_out;
    float* Bv = Ba + (size_t)n_nodes * 128;

    cudaMemsetAsync(d_out, 0, (size_t)out_size * sizeof(float), 0);

    wprep_kernel<<<4, 256>>>(Wm1, Wm2, Wm3, Wy000, Wy110, Wy011, Wy101, Wy111);

    node_proj_kernel<<<(n_nodes + 7) / 8, 256>>>(x_a, x_v, W_L0, W_L1, n_nodes);

    edge_kernel<<<(n_edges + 31) / 32, 256>>>(r_ij, dst, W_enc, b_enc, n_edges);

    cudaFuncSetAttribute(mlp_kernel, cudaFuncAttributeMaxDynamicSharedMemorySize, MLP_DSMEM);
    int ntiles = (n_edges + 63) / 64;
    int grid = ntiles < 148 ? ntiles : 148;
    mlp_kernel<<<grid, 256, MLP_DSMEM>>>(bm1, bm2, src, Ba, Bv, n_edges, ntiles);
}